// round 12
// baseline (speedup 1.0000x reference)
#include <cuda_runtime.h>
#include <cuda_bf16.h>
#include <math.h>

#define B 64
#define TT 512
#define E 128
#define H 256

typedef unsigned long long u64;

// ---------------- packed f32x2 helpers ----------------------------------------
__device__ __forceinline__ u64 ffma2(u64 a, u64 b, u64 c) {
    u64 d;
    asm("fma.rn.f32x2 %0, %1, %2, %3;" : "=l"(d) : "l"(a), "l"(b), "l"(c));
    return d;
}
__device__ __forceinline__ u64 fadd2(u64 a, u64 b) {
    u64 d;
    asm("add.rn.f32x2 %0, %1, %2;" : "=l"(d) : "l"(a), "l"(b));
    return d;
}
__device__ __forceinline__ float2 unpk(u64 v) {
    float2 r;
    asm("mov.b64 {%0, %1}, %2;" : "=f"(r.x), "=f"(r.y) : "l"(v));
    return r;
}
// branchless fast tanh: 1 - 2/(1 + 2^(2x*log2e)); abs err ~1e-6
__device__ __forceinline__ float fast_tanh(float x) {
    float e, r;
    asm("ex2.approx.f32 %0, %1;" : "=f"(e) : "f"(x * 2.885390081777927f));
    asm("rcp.approx.f32 %0, %1;" : "=f"(r) : "f"(e + 1.0f));
    return fmaf(-2.0f, r, 1.0f);
}

// ---------------- scratch (device globals) ------------------------------------
__device__ float g_xp1f[(size_t)B * TT * H];
__device__ float g_xp1b[(size_t)B * TT * H];
__device__ float g_o1[(size_t)B * TT * 2 * H];
__device__ float g_xp2f[(size_t)B * TT * H];
__device__ float g_xp2b[(size_t)B * TT * H];
__device__ float g_o2[(size_t)B * TT * 2 * H];

// pair-packed weights: [k-pair][j] -> float2 {w[2kp][j], w[2kp+1][j]}
__device__ float2 g_p1f[64 * H];
__device__ float2 g_p1b[64 * H];
__device__ float2 g_p2f[256 * H];
__device__ float2 g_p2b[256 * H];
__device__ float2 g_w1p[512 * 512];   // [kp][o], k<1024, o<512
__device__ float2 g_w2p[256 * 256];   // [kp][o], k<512,  o<256
__device__ float g_b1f[H], g_b1b[H], g_b2f[H], g_b2b[H];

// ---------------- prep: pair-packing transposes + bias combine ----------------
__global__ void prep_kernel(
    const float* __restrict__ r1_wif, const float* __restrict__ r1_wib,
    const float* __restrict__ r1_bif, const float* __restrict__ r1_bhf,
    const float* __restrict__ r1_bib, const float* __restrict__ r1_bhb,
    const float* __restrict__ r2_wif, const float* __restrict__ r2_wib,
    const float* __restrict__ r2_bif, const float* __restrict__ r2_bhf,
    const float* __restrict__ r2_bib, const float* __restrict__ r2_bhb,
    const float* __restrict__ w1, const float* __restrict__ w2)
{
    int i = blockIdx.x * 256 + threadIdx.x;
    if (i < 64 * H) {
        int kp = i >> 8, j = i & 255;
        g_p1f[i] = make_float2(r1_wif[j * E + 2 * kp], r1_wif[j * E + 2 * kp + 1]);
        g_p1b[i] = make_float2(r1_wib[j * E + 2 * kp], r1_wib[j * E + 2 * kp + 1]);
    }
    if (i < 256 * H) {
        int kp = i >> 8, j = i & 255;
        g_p2f[i] = make_float2(r2_wif[j * 512 + 2 * kp], r2_wif[j * 512 + 2 * kp + 1]);
        g_p2b[i] = make_float2(r2_wib[j * 512 + 2 * kp], r2_wib[j * 512 + 2 * kp + 1]);
        g_w2p[i] = make_float2(w2[j * 512 + 2 * kp], w2[j * 512 + 2 * kp + 1]);
    }
    if (i < 512 * 512) {
        int kp = i >> 9, o = i & 511;
        g_w1p[i] = make_float2(w1[o * 1024 + 2 * kp], w1[o * 1024 + 2 * kp + 1]);
    }
    if (i < H) {
        g_b1f[i] = r1_bif[i] + r1_bhf[i];
        g_b1b[i] = r1_bib[i] + r1_bhb[i];
        g_b2f[i] = r2_bif[i] + r2_bhf[i];
        g_b2b[i] = r2_bib[i] + r2_bhb[i];
    }
}

// ---------------- layer-1 input projection ------------------------------------
// 256 thr: warps 0-3 = fwd (j=tid, j+128), warps 4-7 = bwd. TTT=16 time tile.
// ev loaded as LDS.128 (2 k-pairs), weights streamed once per 16 tokens.
#define TTT 16
__global__ __launch_bounds__(256, 2) void proj1_kernel(
    const int* __restrict__ x, const float* __restrict__ emb)
{
    __shared__ __align__(16) float e[TTT * E];   // 8KB
    int b = blockIdx.y, t0 = blockIdx.x * TTT;
    int tid = threadIdx.x;
    for (int i = tid; i < TTT * E; i += 256) {
        int tt = i >> 7, k = i & 127;
        int idx = x[b * TT + t0 + tt];
        e[i] = emb[(size_t)idx * E + k];
    }
    __syncthreads();

    int j = tid & 127;
    int isB = tid >> 7;
    const u64* wp = isB ? (const u64*)g_p1b : (const u64*)g_p1f;
    const float* bias = isB ? g_b1b : g_b1f;
    float* outp = isB ? g_xp1b : g_xp1f;
    const ulonglong2* e2 = (const ulonglong2*)e;   // [tt][32] (2 pairs each)

    u64 a0[TTT], a1[TTT];
#pragma unroll
    for (int tt = 0; tt < TTT; tt++) { a0[tt] = a1[tt] = 0ull; }
#pragma unroll 2
    for (int kp2 = 0; kp2 < 32; kp2++) {           // 64 k-pairs as 32 pair-pairs
        u64 w00 = wp[(2 * kp2) * H + j];
        u64 w01 = wp[(2 * kp2 + 1) * H + j];
        u64 w10 = wp[(2 * kp2) * H + j + 128];
        u64 w11 = wp[(2 * kp2 + 1) * H + j + 128];
#pragma unroll
        for (int tt = 0; tt < TTT; tt++) {
            ulonglong2 ev = e2[tt * 32 + kp2];
            a0[tt] = ffma2(ev.x, w00, a0[tt]);
            a0[tt] = ffma2(ev.y, w01, a0[tt]);
            a1[tt] = ffma2(ev.x, w10, a1[tt]);
            a1[tt] = ffma2(ev.y, w11, a1[tt]);
        }
    }
    float b0 = bias[j], b1v = bias[j + 128];
#pragma unroll
    for (int tt = 0; tt < TTT; tt++) {
        size_t o = ((size_t)(b * TT + t0 + tt)) * H;
        float2 v;
        v = unpk(a0[tt]); outp[o + j]       = v.x + v.y + b0;
        v = unpk(a1[tt]); outp[o + j + 128] = v.x + v.y + b1v;
    }
}

// ---------------- layer-2 input projection ------------------------------------
__global__ __launch_bounds__(256, 2) void proj2_kernel()
{
    __shared__ __align__(16) float e[TTT * 2 * H];  // 32KB
    int b = blockIdx.y, t0 = blockIdx.x * TTT;
    const float4* in4 = (const float4*)(g_o1 + ((size_t)(b * TT + t0)) * (2 * H));
    float4* e4 = (float4*)e;
    for (int i = threadIdx.x; i < TTT * 2 * H / 4; i += 256) e4[i] = in4[i];
    __syncthreads();

    int tid = threadIdx.x;
    int j = tid & 127;
    int isB = tid >> 7;
    const u64* wp = isB ? (const u64*)g_p2b : (const u64*)g_p2f;
    const float* bias = isB ? g_b2b : g_b2f;
    float* outp = isB ? g_xp2b : g_xp2f;
    const ulonglong2* e2 = (const ulonglong2*)e;   // [tt][128]

    u64 a0[TTT], a1[TTT];
#pragma unroll
    for (int tt = 0; tt < TTT; tt++) { a0[tt] = a1[tt] = 0ull; }
#pragma unroll 2
    for (int kp2 = 0; kp2 < 128; kp2++) {          // 256 k-pairs as 128 pair-pairs
        u64 w00 = wp[(2 * kp2) * H + j];
        u64 w01 = wp[(2 * kp2 + 1) * H + j];
        u64 w10 = wp[(2 * kp2) * H + j + 128];
        u64 w11 = wp[(2 * kp2 + 1) * H + j + 128];
#pragma unroll
        for (int tt = 0; tt < TTT; tt++) {
            ulonglong2 ev = e2[tt * 128 + kp2];
            a0[tt] = ffma2(ev.x, w00, a0[tt]);
            a0[tt] = ffma2(ev.y, w01, a0[tt]);
            a1[tt] = ffma2(ev.x, w10, a1[tt]);
            a1[tt] = ffma2(ev.y, w11, a1[tt]);
        }
    }
    float b0 = bias[j], b1v = bias[j + 128];
#pragma unroll
    for (int tt = 0; tt < TTT; tt++) {
        size_t o = ((size_t)(b * TT + t0 + tt)) * H;
        float2 v;
        v = unpk(a0[tt]); outp[o + j]       = v.x + v.y + b0;
        v = unpk(a1[tt]); outp[o + j + 128] = v.x + v.y + b1v;
    }
}

// ---------------- recurrence: one CTA per (b,dir), 512 threads, split-K -------
// UNCHANGED from the proven R7/R11 structure. PREG=40 reg pairs, PSM=24 smem
// pairs as 12 ulonglong2 slots [slot][j]; h double-buffered; xp prefetched one
// step ahead; branchless fast_tanh.
constexpr int PREG = 40;
constexpr int PSM = 24;
constexpr int WSLOT = PSM / 2;                    // 12
constexpr int RNN_SMEM_BYTES = 2 * WSLOT * H * 16 + 2 * H * 4 + H * 4;  // 101376

__global__ __launch_bounds__(512, 1) void rnn_kernel(
    const float* __restrict__ whh_f, const float* __restrict__ whh_b, int layer)
{
    extern __shared__ char smraw[];
    ulonglong2* wsq = (ulonglong2*)smraw;                     // [24][256]
    float* hb = (float*)(smraw + 2 * WSLOT * H * 16);         // [2][256]
    float* partial = hb + 2 * H;                              // [256]

    int b = blockIdx.x >> 1;
    int dir = blockIdx.x & 1;
    const float* whh = dir ? whh_b : whh_f;
    const float* xp = layer ? (dir ? g_xp2b : g_xp2f) : (dir ? g_xp1b : g_xp1f);
    float* out = layer ? g_o2 : g_o1;

    int j = threadIdx.x & 255;
    int half = threadIdx.x >> 8;

    const u64* wrow = (const u64*)(whh + (size_t)j * H) + half * 64;
    u64 wr[PREG];
#pragma unroll
    for (int r = 0; r < PREG; r++) wr[r] = wrow[r];
#pragma unroll
    for (int i = 0; i < WSLOT; i++) {
        ulonglong2 v;
        v.x = wrow[PREG + 2 * i];
        v.y = wrow[PREG + 2 * i + 1];
        wsq[(half * WSLOT + i) * H + j] = v;
    }
    if (half == 0) { hb[j] = 0.f; hb[H + j] = 0.f; }
    __syncthreads();

    const float* xpBase = xp + (size_t)b * TT * H + j;
    float* outBase = out + (size_t)b * TT * (2 * H) + dir * H + j;
    const ulonglong2* wsBase = wsq + (half * WSLOT) * H + j;

    float xpv = (half == 0)
        ? xpBase[(size_t)(dir ? (TT - 1) : 0) * H] : 0.f;

    int p = 0;
    for (int s = 0; s < TT; s++) {
        int t = dir ? (TT - 1 - s) : s;
        int sn = (s < TT - 1) ? (s + 1) : s;
        int tn = dir ? (TT - 1 - sn) : sn;
        float xpv_next = (half == 0) ? xpBase[(size_t)tn * H] : 0.f;

        const ulonglong2* h2 = (const ulonglong2*)(hb + p * H) + half * 32;
        u64 a0 = 0ull, a1 = 0ull, a2 = 0ull, a3 = 0ull;
#pragma unroll
        for (int q = 0; q < PREG / 2; q++) {
            ulonglong2 hq = h2[q];
            if (q & 1) {
                a2 = ffma2(hq.x, wr[2 * q], a2);
                a3 = ffma2(hq.y, wr[2 * q + 1], a3);
            } else {
                a0 = ffma2(hq.x, wr[2 * q], a0);
                a1 = ffma2(hq.y, wr[2 * q + 1], a1);
            }
        }
#pragma unroll
        for (int i = 0; i < WSLOT; i++) {
            ulonglong2 hq = h2[PREG / 2 + i];
            ulonglong2 wq = wsBase[i * H];
            if (i & 1) {
                a2 = ffma2(hq.x, wq.x, a2);
                a3 = ffma2(hq.y, wq.y, a3);
            } else {
                a0 = ffma2(hq.x, wq.x, a0);
                a1 = ffma2(hq.y, wq.y, a1);
            }
        }
        float2 f = unpk(fadd2(fadd2(a0, a1), fadd2(a2, a3)));
        float part = f.x + f.y;
        if (half == 1) partial[j] = part;
        __syncthreads();
        if (half == 0) {
            float hn = fast_tanh(part + partial[j] + xpv);
            hb[(p ^ 1) * H + j] = hn;
            outBase[(size_t)t * (2 * H)] = hn;
        }
        __syncthreads();
        xpv = xpv_next;
        p ^= 1;
    }
}

// ---------------- tail: last/mean + LN + FC1(relu) + FC2 ----------------------
__global__ __launch_bounds__(256) void tail_kernel(
    const float* __restrict__ ln_g, const float* __restrict__ ln_b,
    const float* __restrict__ b1, const float* __restrict__ b2,
    float* __restrict__ outp)
{
    __shared__ __align__(16) float h_s[1024];
    __shared__ __align__(16) float hn_s[1024];
    __shared__ float red[256];
    __shared__ __align__(16) float r_s[512];
    int b = blockIdx.x, j = threadIdx.x;

    const float* base = g_o2 + (size_t)b * TT * (2 * H);
    float s0 = 0.f, s1 = 0.f;
    for (int t = 0; t < TT; t++) {
        s0 += base[(size_t)t * (2 * H) + j];
        s1 += base[(size_t)t * (2 * H) + H + j];
    }
    h_s[j]       = base[(size_t)(TT - 1) * (2 * H) + j];
    h_s[H + j]   = base[(size_t)(TT - 1) * (2 * H) + H + j];
    h_s[512 + j] = s0 * (1.f / 512.f);
    h_s[768 + j] = s1 * (1.f / 512.f);
    __syncthreads();

    red[j] = h_s[j] + h_s[j + 256] + h_s[j + 512] + h_s[j + 768];
    __syncthreads();
    for (int off = 128; off > 0; off >>= 1) {
        if (j < off) red[j] += red[j + off];
        __syncthreads();
    }
    float mu = red[0] * (1.f / 1024.f);
    __syncthreads();
    float d0 = h_s[j] - mu, d1 = h_s[j + 256] - mu,
          d2 = h_s[j + 512] - mu, d3 = h_s[j + 768] - mu;
    red[j] = d0 * d0 + d1 * d1 + d2 * d2 + d3 * d3;
    __syncthreads();
    for (int off = 128; off > 0; off >>= 1) {
        if (j < off) red[j] += red[j + off];
        __syncthreads();
    }
    float var = red[0] * (1.f / 1024.f);
    float sc = rsqrtf(var + 1e-5f);
    hn_s[j]       = d0 * sc * ln_g[j]       + ln_b[j];
    hn_s[j + 256] = d1 * sc * ln_g[j + 256] + ln_b[j + 256];
    hn_s[j + 512] = d2 * sc * ln_g[j + 512] + ln_b[j + 512];
    hn_s[j + 768] = d3 * sc * ln_g[j + 768] + ln_b[j + 768];
    __syncthreads();

    {   // FC1: 1024 -> 512, relu
        const u64* hnu = (const u64*)hn_s;
        const u64* w1u = (const u64*)g_w1p;
        u64 acc0 = 0ull, acc1 = 0ull;
#pragma unroll 4
        for (int kp = 0; kp < 512; kp++) {
            u64 hv = hnu[kp];
            acc0 = ffma2(hv, w1u[kp * 512 + j], acc0);
            acc1 = ffma2(hv, w1u[kp * 512 + j + 256], acc1);
        }
        float2 f0 = unpk(acc0), f1 = unpk(acc1);
        r_s[j]       = fmaxf(f0.x + f0.y + b1[j], 0.f);
        r_s[j + 256] = fmaxf(f1.x + f1.y + b1[j + 256], 0.f);
    }
    __syncthreads();

    {   // FC2: 512 -> 256
        const u64* rsu = (const u64*)r_s;
        const u64* w2u = (const u64*)g_w2p;
        u64 acc = 0ull;
#pragma unroll 4
        for (int kp = 0; kp < 256; kp++)
            acc = ffma2(rsu[kp], w2u[kp * 256 + j], acc);
        float2 f = unpk(acc);
        outp[b * 256 + j] = f.x + f.y + b2[j];
    }
}

// ---------------- launch ------------------------------------------------------
extern "C" void kernel_launch(void* const* d_in, const int* in_sizes, int n_in,
                              void* d_out, int out_size)
{
    const int*   x      = (const int*)  d_in[0];
    const float* emb    = (const float*)d_in[1];
    const float* r1_wif = (const float*)d_in[2];
    const float* r1_whf = (const float*)d_in[3];
    const float* r1_bif = (const float*)d_in[4];
    const float* r1_bhf = (const float*)d_in[5];
    const float* r1_wib = (const float*)d_in[6];
    const float* r1_whb = (const float*)d_in[7];
    const float* r1_bib = (const float*)d_in[8];
    const float* r1_bhb = (const float*)d_in[9];
    const float* r2_wif = (const float*)d_in[10];
    const float* r2_whf = (const float*)d_in[11];
    const float* r2_bif = (const float*)d_in[12];
    const float* r2_bhf = (const float*)d_in[13];
    const float* r2_wib = (const float*)d_in[14];
    const float* r2_whb = (const float*)d_in[15];
    const float* r2_bib = (const float*)d_in[16];
    const float* r2_bhb = (const float*)d_in[17];
    const float* ln_g   = (const float*)d_in[18];
    const float* ln_b   = (const float*)d_in[19];
    const float* w1     = (const float*)d_in[20];
    const float* b1     = (const float*)d_in[21];
    const float* w2     = (const float*)d_in[22];
    const float* b2     = (const float*)d_in[23];
    float* outp = (float*)d_out;

    cudaFuncSetAttribute(rnn_kernel,
                         cudaFuncAttributeMaxDynamicSharedMemorySize,
                         RNN_SMEM_BYTES);

    prep_kernel<<<1024, 256>>>(r1_wif, r1_wib, r1_bif, r1_bhf, r1_bib, r1_bhb,
                               r2_wif, r2_wib, r2_bif, r2_bhf, r2_bib, r2_bhb,
                               w1, w2);

    dim3 gproj(TT / TTT, B);
    proj1_kernel<<<gproj, 256>>>(x, emb);
    rnn_kernel<<<2 * B, 512, RNN_SMEM_BYTES>>>(r1_whf, r1_whb, 0);
    proj2_kernel<<<gproj, 256>>>();
    rnn_kernel<<<2 * B, 512, RNN_SMEM_BYTES>>>(r2_whf, r2_whb, 1);
    tail_kernel<<<B, 256>>>(ln_g, ln_b, b1, b2, outp);
}

// round 14
// speedup vs baseline: 1.0907x; 1.0907x over previous
#include <cuda_runtime.h>
#include <cuda_bf16.h>
#include <math.h>
#include <stdint.h>

#define B 64
#define TT 512
#define E 128
#define H 256

typedef unsigned long long u64;

// ---------------- packed f32x2 helpers ----------------------------------------
__device__ __forceinline__ u64 ffma2(u64 a, u64 b, u64 c) {
    u64 d;
    asm("fma.rn.f32x2 %0, %1, %2, %3;" : "=l"(d) : "l"(a), "l"(b), "l"(c));
    return d;
}
__device__ __forceinline__ u64 fadd2(u64 a, u64 b) {
    u64 d;
    asm("add.rn.f32x2 %0, %1, %2;" : "=l"(d) : "l"(a), "l"(b));
    return d;
}
__device__ __forceinline__ float2 unpk(u64 v) {
    float2 r;
    asm("mov.b64 {%0, %1}, %2;" : "=f"(r.x), "=f"(r.y) : "l"(v));
    return r;
}
__device__ __forceinline__ float fast_tanh(float x) {
    float e, r;
    asm("ex2.approx.f32 %0, %1;" : "=f"(e) : "f"(x * 2.885390081777927f));
    asm("rcp.approx.f32 %0, %1;" : "=f"(r) : "f"(e + 1.0f));
    return fmaf(-2.0f, r, 1.0f);
}

// bf16 hi/lo packing (4 values per u64)
__device__ __forceinline__ u64 pack4bf_hi(float4 v) {
    unsigned short s0 = __bfloat16_as_ushort(__float2bfloat16(v.x));
    unsigned short s1 = __bfloat16_as_ushort(__float2bfloat16(v.y));
    unsigned short s2 = __bfloat16_as_ushort(__float2bfloat16(v.z));
    unsigned short s3 = __bfloat16_as_ushort(__float2bfloat16(v.w));
    return (u64)s0 | ((u64)s1 << 16) | ((u64)s2 << 32) | ((u64)s3 << 48);
}
__device__ __forceinline__ u64 pack4bf_lo(float4 v) {
    float r0 = v.x - __bfloat162float(__float2bfloat16(v.x));
    float r1 = v.y - __bfloat162float(__float2bfloat16(v.y));
    float r2 = v.z - __bfloat162float(__float2bfloat16(v.z));
    float r3 = v.w - __bfloat162float(__float2bfloat16(v.w));
    unsigned short s0 = __bfloat16_as_ushort(__float2bfloat16(r0));
    unsigned short s1 = __bfloat16_as_ushort(__float2bfloat16(r1));
    unsigned short s2 = __bfloat16_as_ushort(__float2bfloat16(r2));
    unsigned short s3 = __bfloat16_as_ushort(__float2bfloat16(r3));
    return (u64)s0 | ((u64)s1 << 16) | ((u64)s2 << 32) | ((u64)s3 << 48);
}

// warp-level bf16 MMA (sm_80+ path, valid on plain sm_103)
#define MMA_BF16(c, a0, a1, a2, a3, b0, b1)                                    \
    asm volatile(                                                              \
        "mma.sync.aligned.m16n8k16.row.col.f32.bf16.bf16.f32 "                 \
        "{%0,%1,%2,%3}, {%4,%5,%6,%7}, {%8,%9}, {%0,%1,%2,%3};\n"              \
        : "+f"((c)[0]), "+f"((c)[1]), "+f"((c)[2]), "+f"((c)[3])               \
        : "r"(a0), "r"(a1), "r"(a2), "r"(a3), "r"(b0), "r"(b1))

// ---------------- scratch (device globals) ------------------------------------
__device__ float g_xp1f[(size_t)B * TT * H];
__device__ float g_xp1b[(size_t)B * TT * H];
__device__ float g_o1[(size_t)B * TT * 2 * H];
__device__ float g_xp2f[(size_t)B * TT * H];
__device__ float g_xp2b[(size_t)B * TT * H];
__device__ float g_o2[(size_t)B * TT * 2 * H];

__device__ float2 g_p1f[64 * H];
__device__ float2 g_p1b[64 * H];
__device__ float2 g_w1p[512 * 512];
__device__ float2 g_w2p[256 * 256];
__device__ float g_b1f[H], g_b1b[H], g_b2f[H], g_b2b[H];

// bf16 hi/lo split of layer-2 input-proj weights, [n=256][k/4=128] u64
__device__ u64 g_w2fh[256 * 128];
__device__ u64 g_w2fl[256 * 128];
__device__ u64 g_w2bh[256 * 128];
__device__ u64 g_w2bl[256 * 128];

// ---------------- prep --------------------------------------------------------
__global__ void prep_kernel(
    const float* __restrict__ r1_wif, const float* __restrict__ r1_wib,
    const float* __restrict__ r1_bif, const float* __restrict__ r1_bhf,
    const float* __restrict__ r1_bib, const float* __restrict__ r1_bhb,
    const float* __restrict__ r2_wif, const float* __restrict__ r2_wib,
    const float* __restrict__ r2_bif, const float* __restrict__ r2_bhf,
    const float* __restrict__ r2_bib, const float* __restrict__ r2_bhb,
    const float* __restrict__ w1, const float* __restrict__ w2)
{
    int i = blockIdx.x * 256 + threadIdx.x;
    if (i < 64 * H) {
        int kp = i >> 8, j = i & 255;
        g_p1f[i] = make_float2(r1_wif[j * E + 2 * kp], r1_wif[j * E + 2 * kp + 1]);
        g_p1b[i] = make_float2(r1_wib[j * E + 2 * kp], r1_wib[j * E + 2 * kp + 1]);
    }
    if (i < 256 * H) {
        int kp = i >> 8, j = i & 255;
        g_w2p[i] = make_float2(w2[j * 512 + 2 * kp], w2[j * 512 + 2 * kp + 1]);
    }
    if (i < 256 * 128) {                   // bf16 hi/lo split, 4 k's per slot
        float4 vf = *(const float4*)(r2_wif + (size_t)i * 4);
        float4 vb = *(const float4*)(r2_wib + (size_t)i * 4);
        g_w2fh[i] = pack4bf_hi(vf);
        g_w2fl[i] = pack4bf_lo(vf);
        g_w2bh[i] = pack4bf_hi(vb);
        g_w2bl[i] = pack4bf_lo(vb);
    }
    if (i < 512 * 512) {
        int kp = i >> 9, o = i & 511;
        g_w1p[i] = make_float2(w1[o * 1024 + 2 * kp], w1[o * 1024 + 2 * kp + 1]);
    }
    if (i < H) {
        g_b1f[i] = r1_bif[i] + r1_bhf[i];
        g_b1b[i] = r1_bib[i] + r1_bhb[i];
        g_b2f[i] = r2_bif[i] + r2_bhf[i];
        g_b2b[i] = r2_bib[i] + r2_bhb[i];
    }
}

// ---------------- layer-1 input projection (R7-proven SIMT) -------------------
#define TT1 8
__global__ __launch_bounds__(128) void proj1_kernel(
    const int* __restrict__ x, const float* __restrict__ emb)
{
    __shared__ __align__(16) float e[TT1][E];
    int b = blockIdx.y, t0 = blockIdx.x * TT1;
    int tid = threadIdx.x;
    for (int i = tid; i < TT1 * E; i += 128) {
        int tt = i >> 7, k = i & 127;
        int idx = x[b * TT + t0 + tt];
        e[tt][k] = emb[(size_t)idx * E + k];
    }
    __syncthreads();
    int j = tid;
    const u64* wfp = (const u64*)g_p1f;
    const u64* wbp = (const u64*)g_p1b;
    u64 af0[TT1], af1[TT1], ab0[TT1], ab1[TT1];
#pragma unroll
    for (int tt = 0; tt < TT1; tt++) { af0[tt] = af1[tt] = ab0[tt] = ab1[tt] = 0ull; }
#pragma unroll 2
    for (int kp = 0; kp < 64; kp++) {
        u64 wf0 = wfp[kp * H + j];
        u64 wf1 = wfp[kp * H + j + 128];
        u64 wb0 = wbp[kp * H + j];
        u64 wb1 = wbp[kp * H + j + 128];
#pragma unroll
        for (int tt = 0; tt < TT1; tt++) {
            u64 ev = *(const u64*)&e[tt][2 * kp];
            af0[tt] = ffma2(ev, wf0, af0[tt]);
            af1[tt] = ffma2(ev, wf1, af1[tt]);
            ab0[tt] = ffma2(ev, wb0, ab0[tt]);
            ab1[tt] = ffma2(ev, wb1, ab1[tt]);
        }
    }
    float bf0 = g_b1f[j], bf1 = g_b1f[j + 128];
    float bb0 = g_b1b[j], bb1 = g_b1b[j + 128];
#pragma unroll
    for (int tt = 0; tt < TT1; tt++) {
        size_t o = ((size_t)(b * TT + t0 + tt)) * H;
        float2 v;
        v = unpk(af0[tt]); g_xp1f[o + j]       = v.x + v.y + bf0;
        v = unpk(af1[tt]); g_xp1f[o + j + 128] = v.x + v.y + bf1;
        v = unpk(ab0[tt]); g_xp1b[o + j]       = v.x + v.y + bb0;
        v = unpk(ab1[tt]); g_xp1b[o + j + 128] = v.x + v.y + bb1;
    }
}

// ---------------- layer-2 input projection: warp-level bf16 MMA GEMM ----------
// Per CTA: 64 tokens (M), N=512 (fwd 256 | bwd 256), K=512.
// D = Ah*Bh + Ah*Bl + Al*Bh (fp32 accum).
// A smem: bf16, row stride 520 elems (bank-conflict-free: bank=4r+c).
// B smem: bf16, row stride 72 elems  (bank-conflict-free: bank=4n+c).
// Warp tile m32 x n32; supertile n128, looped 4x; K chunked 8 x 64.
static constexpr int AK = 520;                       // A row stride (elems)
static constexpr int A_H_OFF = 0;                    // Ah base
static constexpr int A_L_OFF = 64 * AK * 2;          // 66,560
static constexpr int BSTRIDE = 72;                   // B row stride (elems)
static constexpr int B_H_OFF = A_L_OFF + 64 * AK * 2;      // 133,120
static constexpr int B_L_OFF = B_H_OFF + 128 * BSTRIDE * 2; // 151,552
static constexpr int P2_SMEM = B_L_OFF + 128 * BSTRIDE * 2; // 169,984

__global__ __launch_bounds__(256, 1) void proj2_mma_kernel()
{
    extern __shared__ char smem[];
    int tid = threadIdx.x;
    int wid = tid >> 5, lane = tid & 31;
    int r4 = lane >> 2;                   // 0..7
    int kp2 = (lane & 3) * 2;             // 0,2,4,6
    int tok0 = blockIdx.x * 64;

    // ---- stage A: o1[tok0..tok0+64) fp32 -> bf16 hi/lo, padded stride ----
    for (int idx = tid; idx < 64 * 128; idx += 256) {
        int m = idx >> 7, q = idx & 127;  // q: float4 within 512-k row
        float4 v = *(const float4*)(g_o1 + (size_t)(tok0 + m) * 512 + q * 4);
        uint32_t off = (uint32_t)(m * AK + q * 4) * 2;
        *(u64*)(smem + A_H_OFF + off) = pack4bf_hi(v);
        *(u64*)(smem + A_L_OFF + off) = pack4bf_lo(v);
    }

    int mg = wid & 1;                     // m32 group (rows mg*32..mg*32+31)
    int nq = wid >> 1;                    // n32 quarter within supertile n128
    int M0 = mg * 32;
    int N0 = nq * 32;

    for (int nc = 0; nc < 4; nc++) {      // supertile: global n = nc*128 + ...
        const u64* gBh = (nc < 2) ? g_w2fh : g_w2bh;
        const u64* gBl = (nc < 2) ? g_w2fl : g_w2bl;
        int nbase = (nc & 1) * 128;       // within the 256-wide fwd/bwd array

        float acc[2][4][4];
#pragma unroll
        for (int mt = 0; mt < 2; mt++)
#pragma unroll
            for (int nt = 0; nt < 4; nt++)
#pragma unroll
                for (int q = 0; q < 4; q++) acc[mt][nt][q] = 0.f;

        for (int kc = 0; kc < 8; kc++) {
            __syncthreads();              // protect prev compute before refill
            // ---- stage B chunk: n128 x k64 hi/lo ----
            for (int idx = tid; idx < 128 * 16; idx += 256) {
                int n = idx >> 4, kq = idx & 15;
                size_t gi = (size_t)(nbase + n) * 128 + kc * 16 + kq;
                uint32_t off = (uint32_t)(n * BSTRIDE * 2 + kq * 8);
                *(u64*)(smem + B_H_OFF + off) = gBh[gi];
                *(u64*)(smem + B_L_OFF + off) = gBl[gi];
            }
            __syncthreads();

#pragma unroll
            for (int ks = 0; ks < 4; ks++) {
                int kg = kc * 64 + ks * 16;       // A: global k
                int kl = ks * 16;                 // B: local k
                uint32_t ah[2][4], al[2][4];
#pragma unroll
                for (int mt = 0; mt < 2; mt++) {
                    uint32_t ba = (uint32_t)(((M0 + mt * 16 + r4) * AK + kg + kp2) * 2);
                    ah[mt][0] = *(const uint32_t*)(smem + A_H_OFF + ba);
                    ah[mt][1] = *(const uint32_t*)(smem + A_H_OFF + ba + 8 * AK * 2);
                    ah[mt][2] = *(const uint32_t*)(smem + A_H_OFF + ba + 16);
                    ah[mt][3] = *(const uint32_t*)(smem + A_H_OFF + ba + 8 * AK * 2 + 16);
                    al[mt][0] = *(const uint32_t*)(smem + A_L_OFF + ba);
                    al[mt][1] = *(const uint32_t*)(smem + A_L_OFF + ba + 8 * AK * 2);
                    al[mt][2] = *(const uint32_t*)(smem + A_L_OFF + ba + 16);
                    al[mt][3] = *(const uint32_t*)(smem + A_L_OFF + ba + 8 * AK * 2 + 16);
                }
#pragma unroll
                for (int nt = 0; nt < 4; nt++) {
                    uint32_t bb = (uint32_t)((N0 + nt * 8 + r4) * BSTRIDE * 2 + (kl + kp2) * 2);
                    uint32_t bh0 = *(const uint32_t*)(smem + B_H_OFF + bb);
                    uint32_t bh1 = *(const uint32_t*)(smem + B_H_OFF + bb + 16);
                    uint32_t bl0 = *(const uint32_t*)(smem + B_L_OFF + bb);
                    uint32_t bl1 = *(const uint32_t*)(smem + B_L_OFF + bb + 16);
#pragma unroll
                    for (int mt = 0; mt < 2; mt++) {
                        MMA_BF16(acc[mt][nt], ah[mt][0], ah[mt][1], ah[mt][2], ah[mt][3], bh0, bh1);
                        MMA_BF16(acc[mt][nt], ah[mt][0], ah[mt][1], ah[mt][2], ah[mt][3], bl0, bl1);
                        MMA_BF16(acc[mt][nt], al[mt][0], al[mt][1], al[mt][2], al[mt][3], bh0, bh1);
                    }
                }
            }
        }

        // ---- write out this supertile ----
        float* outp = (nc < 2) ? g_xp2f : g_xp2b;
        const float* bias = (nc < 2) ? g_b2f : g_b2b;
#pragma unroll
        for (int mt = 0; mt < 2; mt++) {
#pragma unroll
            for (int nt = 0; nt < 4; nt++) {
                int gcol = nbase + N0 + nt * 8 + kp2;
                int row0 = tok0 + M0 + mt * 16 + r4;
                float b0 = bias[gcol], b1v = bias[gcol + 1];
                float2 v0 = make_float2(acc[mt][nt][0] + b0, acc[mt][nt][1] + b1v);
                float2 v1 = make_float2(acc[mt][nt][2] + b0, acc[mt][nt][3] + b1v);
                *(float2*)(outp + (size_t)row0 * H + gcol) = v0;
                *(float2*)(outp + (size_t)(row0 + 8) * H + gcol) = v1;
            }
        }
    }
}

// ---------------- recurrence (unchanged, proven) -------------------------------
constexpr int PREG = 40;
constexpr int PSM = 24;
constexpr int WSLOT = PSM / 2;
constexpr int RNN_SMEM_BYTES = 2 * WSLOT * H * 16 + 2 * H * 4 + H * 4;

__global__ __launch_bounds__(512, 1) void rnn_kernel(
    const float* __restrict__ whh_f, const float* __restrict__ whh_b, int layer)
{
    extern __shared__ char smraw[];
    ulonglong2* wsq = (ulonglong2*)smraw;
    float* hb = (float*)(smraw + 2 * WSLOT * H * 16);
    float* partial = hb + 2 * H;

    int b = blockIdx.x >> 1;
    int dir = blockIdx.x & 1;
    const float* whh = dir ? whh_b : whh_f;
    const float* xp = layer ? (dir ? g_xp2b : g_xp2f) : (dir ? g_xp1b : g_xp1f);
    float* out = layer ? g_o2 : g_o1;

    int j = threadIdx.x & 255;
    int half = threadIdx.x >> 8;

    const u64* wrow = (const u64*)(whh + (size_t)j * H) + half * 64;
    u64 wr[PREG];
#pragma unroll
    for (int r = 0; r < PREG; r++) wr[r] = wrow[r];
#pragma unroll
    for (int i = 0; i < WSLOT; i++) {
        ulonglong2 v;
        v.x = wrow[PREG + 2 * i];
        v.y = wrow[PREG + 2 * i + 1];
        wsq[(half * WSLOT + i) * H + j] = v;
    }
    if (half == 0) { hb[j] = 0.f; hb[H + j] = 0.f; }
    __syncthreads();

    const float* xpBase = xp + (size_t)b * TT * H + j;
    float* outBase = out + (size_t)b * TT * (2 * H) + dir * H + j;
    const ulonglong2* wsBase = wsq + (half * WSLOT) * H + j;

    float xpv = (half == 0) ? xpBase[(size_t)(dir ? (TT - 1) : 0) * H] : 0.f;

    int p = 0;
    for (int s = 0; s < TT; s++) {
        int t = dir ? (TT - 1 - s) : s;
        int sn = (s < TT - 1) ? (s + 1) : s;
        int tn = dir ? (TT - 1 - sn) : sn;
        float xpv_next = (half == 0) ? xpBase[(size_t)tn * H] : 0.f;

        const ulonglong2* h2 = (const ulonglong2*)(hb + p * H) + half * 32;
        u64 a0 = 0ull, a1 = 0ull, a2 = 0ull, a3 = 0ull;
#pragma unroll
        for (int q = 0; q < PREG / 2; q++) {
            ulonglong2 hq = h2[q];
            if (q & 1) {
                a2 = ffma2(hq.x, wr[2 * q], a2);
                a3 = ffma2(hq.y, wr[2 * q + 1], a3);
            } else {
                a0 = ffma2(hq.x, wr[2 * q], a0);
                a1 = ffma2(hq.y, wr[2 * q + 1], a1);
            }
        }
#pragma unroll
        for (int i = 0; i < WSLOT; i++) {
            ulonglong2 hq = h2[PREG / 2 + i];
            ulonglong2 wq = wsBase[i * H];
            if (i & 1) {
                a2 = ffma2(hq.x, wq.x, a2);
                a3 = ffma2(hq.y, wq.y, a3);
            } else {
                a0 = ffma2(hq.x, wq.x, a0);
                a1 = ffma2(hq.y, wq.y, a1);
            }
        }
        float2 f = unpk(fadd2(fadd2(a0, a1), fadd2(a2, a3)));
        float part = f.x + f.y;
        if (half == 1) partial[j] = part;
        __syncthreads();
        if (half == 0) {
            float hn = fast_tanh(part + partial[j] + xpv);
            hb[(p ^ 1) * H + j] = hn;
            outBase[(size_t)t * (2 * H)] = hn;
        }
        __syncthreads();
        xpv = xpv_next;
        p ^= 1;
    }
}

// ---------------- tail (unchanged) --------------------------------------------
__global__ __launch_bounds__(256) void tail_kernel(
    const float* __restrict__ ln_g, const float* __restrict__ ln_b,
    const float* __restrict__ b1, const float* __restrict__ b2,
    float* __restrict__ outp)
{
    __shared__ __align__(16) float h_s[1024];
    __shared__ __align__(16) float hn_s[1024];
    __shared__ float red[256];
    __shared__ __align__(16) float r_s[512];
    int b = blockIdx.x, j = threadIdx.x;

    const float* base = g_o2 + (size_t)b * TT * (2 * H);
    float s0 = 0.f, s1 = 0.f;
    for (int t = 0; t < TT; t++) {
        s0 += base[(size_t)t * (2 * H) + j];
        s1 += base[(size_t)t * (2 * H) + H + j];
    }
    h_s[j]       = base[(size_t)(TT - 1) * (2 * H) + j];
    h_s[H + j]   = base[(size_t)(TT - 1) * (2 * H) + H + j];
    h_s[512 + j] = s0 * (1.f / 512.f);
    h_s[768 + j] = s1 * (1.f / 512.f);
    __syncthreads();

    red[j] = h_s[j] + h_s[j + 256] + h_s[j + 512] + h_s[j + 768];
    __syncthreads();
    for (int off = 128; off > 0; off >>= 1) {
        if (j < off) red[j] += red[j + off];
        __syncthreads();
    }
    float mu = red[0] * (1.f / 1024.f);
    __syncthreads();
    float d0 = h_s[j] - mu, d1 = h_s[j + 256] - mu,
          d2 = h_s[j + 512] - mu, d3 = h_s[j + 768] - mu;
    red[j] = d0 * d0 + d1 * d1 + d2 * d2 + d3 * d3;
    __syncthreads();
    for (int off = 128; off > 0; off >>= 1) {
        if (j < off) red[j] += red[j + off];
        __syncthreads();
    }
    float var = red[0] * (1.f / 1024.f);
    float sc = rsqrtf(var + 1e-5f);
    hn_s[j]       = d0 * sc * ln_g[j]       + ln_b[j];
    hn_s[j + 256] = d1 * sc * ln_g[j + 256] + ln_b[j + 256];
    hn_s[j + 512] = d2 * sc * ln_g[j + 512] + ln_b[j + 512];
    hn_s[j + 768] = d3 * sc * ln_g[j + 768] + ln_b[j + 768];
    __syncthreads();

    {
        const u64* hnu = (const u64*)hn_s;
        const u64* w1u = (const u64*)g_w1p;
        u64 acc0 = 0ull, acc1 = 0ull;
#pragma unroll 4
        for (int kp = 0; kp < 512; kp++) {
            u64 hv = hnu[kp];
            acc0 = ffma2(hv, w1u[kp * 512 + j], acc0);
            acc1 = ffma2(hv, w1u[kp * 512 + j + 256], acc1);
        }
        float2 f0 = unpk(acc0), f1 = unpk(acc1);
        r_s[j]       = fmaxf(f0.x + f0.y + b1[j], 0.f);
        r_s[j + 256] = fmaxf(f1.x + f1.y + b1[j + 256], 0.f);
    }
    __syncthreads();

    {
        const u64* rsu = (const u64*)r_s;
        const u64* w2u = (const u64*)g_w2p;
        u64 acc = 0ull;
#pragma unroll 4
        for (int kp = 0; kp < 256; kp++)
            acc = ffma2(rsu[kp], w2u[kp * 256 + j], acc);
        float2 f = unpk(acc);
        outp[b * 256 + j] = f.x + f.y + b2[j];
    }
}

// ---------------- launch ------------------------------------------------------
extern "C" void kernel_launch(void* const* d_in, const int* in_sizes, int n_in,
                              void* d_out, int out_size)
{
    const int*   x      = (const int*)  d_in[0];
    const float* emb    = (const float*)d_in[1];
    const float* r1_wif = (const float*)d_in[2];
    const float* r1_whf = (const float*)d_in[3];
    const float* r1_bif = (const float*)d_in[4];
    const float* r1_bhf = (const float*)d_in[5];
    const float* r1_wib = (const float*)d_in[6];
    const float* r1_whb = (const float*)d_in[7];
    const float* r1_bib = (const float*)d_in[8];
    const float* r1_bhb = (const float*)d_in[9];
    const float* r2_wif = (const float*)d_in[10];
    const float* r2_whf = (const float*)d_in[11];
    const float* r2_bif = (const float*)d_in[12];
    const float* r2_bhf = (const float*)d_in[13];
    const float* r2_wib = (const float*)d_in[14];
    const float* r2_whb = (const float*)d_in[15];
    const float* r2_bib = (const float*)d_in[16];
    const float* r2_bhb = (const float*)d_in[17];
    const float* ln_g   = (const float*)d_in[18];
    const float* ln_b   = (const float*)d_in[19];
    const float* w1     = (const float*)d_in[20];
    const float* b1     = (const float*)d_in[21];
    const float* w2     = (const float*)d_in[22];
    const float* b2     = (const float*)d_in[23];
    float* outp = (float*)d_out;

    cudaFuncSetAttribute(rnn_kernel,
                         cudaFuncAttributeMaxDynamicSharedMemorySize,
                         RNN_SMEM_BYTES);
    cudaFuncSetAttribute(proj2_mma_kernel,
                         cudaFuncAttributeMaxDynamicSharedMemorySize,
                         P2_SMEM);

    prep_kernel<<<1024, 256>>>(r1_wif, r1_wib, r1_bif, r1_bhf, r1_bib, r1_bhb,
                               r2_wif, r2_wib, r2_bif, r2_bhf, r2_bib, r2_bhb,
                               w1, w2);

    dim3 gproj(TT / TT1, B);
    proj1_kernel<<<gproj, 128>>>(x, emb);
    rnn_kernel<<<2 * B, 512, RNN_SMEM_BYTES>>>(r1_whf, r1_whb, 0);
    proj2_mma_kernel<<<(B * TT) / 64, 256, P2_SMEM>>>();
    rnn_kernel<<<2 * B, 512, RNN_SMEM_BYTES>>>(r2_whf, r2_whb, 1);
    tail_kernel<<<B, 256>>>(ln_g, ln_b, b1, b2, outp);
}

// round 15
// speedup vs baseline: 1.1445x; 1.0493x over previous
#include <cuda_runtime.h>
#include <cuda_bf16.h>
#include <math.h>
#include <stdint.h>

#define B 64
#define TT 512
#define E 128
#define H 256

typedef unsigned long long u64;

// ---------------- packed f32x2 helpers ----------------------------------------
__device__ __forceinline__ u64 ffma2(u64 a, u64 b, u64 c) {
    u64 d;
    asm("fma.rn.f32x2 %0, %1, %2, %3;" : "=l"(d) : "l"(a), "l"(b), "l"(c));
    return d;
}
__device__ __forceinline__ u64 fadd2(u64 a, u64 b) {
    u64 d;
    asm("add.rn.f32x2 %0, %1, %2;" : "=l"(d) : "l"(a), "l"(b));
    return d;
}
__device__ __forceinline__ float2 unpk(u64 v) {
    float2 r;
    asm("mov.b64 {%0, %1}, %2;" : "=f"(r.x), "=f"(r.y) : "l"(v));
    return r;
}
__device__ __forceinline__ float fast_tanh(float x) {
    float e, r;
    asm("ex2.approx.f32 %0, %1;" : "=f"(e) : "f"(x * 2.885390081777927f));
    asm("rcp.approx.f32 %0, %1;" : "=f"(r) : "f"(e + 1.0f));
    return fmaf(-2.0f, r, 1.0f);
}

// bf16 hi/lo packing (4 values per u64)
__device__ __forceinline__ u64 pack4bf_hi(float4 v) {
    unsigned short s0 = __bfloat16_as_ushort(__float2bfloat16(v.x));
    unsigned short s1 = __bfloat16_as_ushort(__float2bfloat16(v.y));
    unsigned short s2 = __bfloat16_as_ushort(__float2bfloat16(v.z));
    unsigned short s3 = __bfloat16_as_ushort(__float2bfloat16(v.w));
    return (u64)s0 | ((u64)s1 << 16) | ((u64)s2 << 32) | ((u64)s3 << 48);
}
__device__ __forceinline__ u64 pack4bf_lo(float4 v) {
    float r0 = v.x - __bfloat162float(__float2bfloat16(v.x));
    float r1 = v.y - __bfloat162float(__float2bfloat16(v.y));
    float r2 = v.z - __bfloat162float(__float2bfloat16(v.z));
    float r3 = v.w - __bfloat162float(__float2bfloat16(v.w));
    unsigned short s0 = __bfloat16_as_ushort(__float2bfloat16(r0));
    unsigned short s1 = __bfloat16_as_ushort(__float2bfloat16(r1));
    unsigned short s2 = __bfloat16_as_ushort(__float2bfloat16(r2));
    unsigned short s3 = __bfloat16_as_ushort(__float2bfloat16(r3));
    return (u64)s0 | ((u64)s1 << 16) | ((u64)s2 << 32) | ((u64)s3 << 48);
}

// warp-level bf16 MMA (sm_80+ path, valid on plain sm_103) — layout proven R14
#define MMA_BF16(c, a0, a1, a2, a3, b0, b1)                                    \
    asm volatile(                                                              \
        "mma.sync.aligned.m16n8k16.row.col.f32.bf16.bf16.f32 "                 \
        "{%0,%1,%2,%3}, {%4,%5,%6,%7}, {%8,%9}, {%0,%1,%2,%3};\n"              \
        : "+f"((c)[0]), "+f"((c)[1]), "+f"((c)[2]), "+f"((c)[3])               \
        : "r"(a0), "r"(a1), "r"(a2), "r"(a3), "r"(b0), "r"(b1))

// ---------------- scratch (device globals) ------------------------------------
__device__ float g_xp1f[(size_t)B * TT * H];
__device__ float g_xp1b[(size_t)B * TT * H];
__device__ float g_o1[(size_t)B * TT * 2 * H];
__device__ float g_xp2f[(size_t)B * TT * H];
__device__ float g_xp2b[(size_t)B * TT * H];
__device__ float g_o2[(size_t)B * TT * 2 * H];

__device__ float2 g_w1p[512 * 512];
__device__ float2 g_w2p[256 * 256];
__device__ float g_b1f[H], g_b1b[H], g_b2f[H], g_b2b[H];

// bf16 hi/lo split weights. layer2 in-proj: [n=256][k512/4=128] u64
__device__ u64 g_w2fh[256 * 128];
__device__ u64 g_w2fl[256 * 128];
__device__ u64 g_w2bh[256 * 128];
__device__ u64 g_w2bl[256 * 128];
// layer1 in-proj: [n=256][k128/4=32] u64
__device__ u64 g_r1fh[256 * 32];
__device__ u64 g_r1fl[256 * 32];
__device__ u64 g_r1bh[256 * 32];
__device__ u64 g_r1bl[256 * 32];

// ---------------- prep --------------------------------------------------------
__global__ void prep_kernel(
    const float* __restrict__ r1_wif, const float* __restrict__ r1_wib,
    const float* __restrict__ r1_bif, const float* __restrict__ r1_bhf,
    const float* __restrict__ r1_bib, const float* __restrict__ r1_bhb,
    const float* __restrict__ r2_wif, const float* __restrict__ r2_wib,
    const float* __restrict__ r2_bif, const float* __restrict__ r2_bhf,
    const float* __restrict__ r2_bib, const float* __restrict__ r2_bhb,
    const float* __restrict__ w1, const float* __restrict__ w2)
{
    int i = blockIdx.x * 256 + threadIdx.x;
    if (i < 256 * 32) {                    // layer-1 weights hi/lo
        float4 vf = *(const float4*)(r1_wif + (size_t)i * 4);
        float4 vb = *(const float4*)(r1_wib + (size_t)i * 4);
        g_r1fh[i] = pack4bf_hi(vf);
        g_r1fl[i] = pack4bf_lo(vf);
        g_r1bh[i] = pack4bf_hi(vb);
        g_r1bl[i] = pack4bf_lo(vb);
    }
    if (i < 256 * H) {
        int kp = i >> 8, j = i & 255;
        g_w2p[i] = make_float2(w2[j * 512 + 2 * kp], w2[j * 512 + 2 * kp + 1]);
    }
    if (i < 256 * 128) {                   // layer-2 weights hi/lo
        float4 vf = *(const float4*)(r2_wif + (size_t)i * 4);
        float4 vb = *(const float4*)(r2_wib + (size_t)i * 4);
        g_w2fh[i] = pack4bf_hi(vf);
        g_w2fl[i] = pack4bf_lo(vf);
        g_w2bh[i] = pack4bf_hi(vb);
        g_w2bl[i] = pack4bf_lo(vb);
    }
    if (i < 512 * 512) {
        int kp = i >> 9, o = i & 511;
        g_w1p[i] = make_float2(w1[o * 1024 + 2 * kp], w1[o * 1024 + 2 * kp + 1]);
    }
    if (i < H) {
        g_b1f[i] = r1_bif[i] + r1_bhf[i];
        g_b1b[i] = r1_bib[i] + r1_bhb[i];
        g_b2f[i] = r2_bif[i] + r2_bhf[i];
        g_b2b[i] = r2_bib[i] + r2_bhb[i];
    }
}

// ---------------- shared MMA-projection geometry -------------------------------
// A chunk: 64 rows x 64 k bf16, row stride 72 elems (bank = 4r + c, conflict-free)
// B chunk: 128 rows x 64 k bf16, stride 72.
// smem: A[2 bufs][hi|lo] 9216B each; B[2 bufs][hi|lo] 18432B each.
static constexpr int SA_SZ = 64 * 72 * 2;            // 9216
static constexpr int SB_SZ = 128 * 72 * 2;           // 18432
static constexpr int SB_BASE = 4 * SA_SZ;            // 36864
static constexpr int PJ_SMEM = SB_BASE + 4 * SB_SZ;  // 110592
#define SA_H(buf) ((buf) * 2 * SA_SZ)
#define SA_L(buf) ((buf) * 2 * SA_SZ + SA_SZ)
#define SB_H(buf) (SB_BASE + (buf) * 2 * SB_SZ)
#define SB_L(buf) (SB_BASE + (buf) * 2 * SB_SZ + SB_SZ)

// compute one (m64 x n128 x k64) stage into acc[2][2][4]
#define PJ_COMPUTE(accn, sah, sal, sbh, sbl)                                   \
    do {                                                                       \
        _Pragma("unroll")                                                      \
        for (int ks = 0; ks < 4; ks++) {                                       \
            uint32_t ah[2][4], al[2][4];                                       \
            _Pragma("unroll")                                                  \
            for (int mt = 0; mt < 2; mt++) {                                   \
                uint32_t ba = (uint32_t)(((M0 + mt * 16 + r4) * 72 + ks * 16 + kp2) * 2); \
                ah[mt][0] = *(const uint32_t*)(smem + (sah) + ba);             \
                ah[mt][1] = *(const uint32_t*)(smem + (sah) + ba + 1152);      \
                ah[mt][2] = *(const uint32_t*)(smem + (sah) + ba + 16);        \
                ah[mt][3] = *(const uint32_t*)(smem + (sah) + ba + 1168);      \
                al[mt][0] = *(const uint32_t*)(smem + (sal) + ba);             \
                al[mt][1] = *(const uint32_t*)(smem + (sal) + ba + 1152);      \
                al[mt][2] = *(const uint32_t*)(smem + (sal) + ba + 16);        \
                al[mt][3] = *(const uint32_t*)(smem + (sal) + ba + 1168);      \
            }                                                                  \
            _Pragma("unroll")                                                  \
            for (int nt = 0; nt < 2; nt++) {                                   \
                uint32_t bb = (uint32_t)(((N0 + nt * 8 + r4) * 72 + ks * 16 + kp2) * 2); \
                uint32_t bh0 = *(const uint32_t*)(smem + (sbh) + bb);          \
                uint32_t bh1 = *(const uint32_t*)(smem + (sbh) + bb + 16);     \
                uint32_t bl0 = *(const uint32_t*)(smem + (sbl) + bb);          \
                uint32_t bl1 = *(const uint32_t*)(smem + (sbl) + bb + 16);     \
                _Pragma("unroll")                                              \
                for (int mt = 0; mt < 2; mt++) {                               \
                    MMA_BF16((accn)[mt][nt], ah[mt][0], ah[mt][1], ah[mt][2], ah[mt][3], bh0, bh1); \
                    MMA_BF16((accn)[mt][nt], ah[mt][0], ah[mt][1], ah[mt][2], ah[mt][3], bl0, bl1); \
                    MMA_BF16((accn)[mt][nt], al[mt][0], al[mt][1], al[mt][2], al[mt][3], bh0, bh1); \
                }                                                              \
            }                                                                  \
        }                                                                      \
    } while (0)

// ---------------- layer-2 input projection: HMMA, 512 thr, double-buffered ----
__global__ __launch_bounds__(512, 1) void proj2_mma_kernel()
{
    extern __shared__ char smem[];
    int tid = threadIdx.x;
    int wid = tid >> 5, lane = tid & 31;
    int r4 = lane >> 2;
    int kp2 = (lane & 3) * 2;
    int tok0 = blockIdx.x * 64;
    int M0 = (wid & 1) * 32;
    int N0 = (wid >> 1) * 16;

    float acc[4][2][2][4];
#pragma unroll
    for (int nc = 0; nc < 4; nc++)
#pragma unroll
        for (int mt = 0; mt < 2; mt++)
#pragma unroll
            for (int nt = 0; nt < 2; nt++)
#pragma unroll
                for (int q = 0; q < 4; q++) acc[nc][mt][nt][q] = 0.f;

    // ---- staging lambdas ----
    auto stageA = [&](int kc, int buf) {
#pragma unroll
        for (int idx = tid; idx < 64 * 16; idx += 512) {
            int m = idx >> 4, q = idx & 15;
            float4 v = *(const float4*)(g_o1 + (size_t)(tok0 + m) * 512 + kc * 64 + q * 4);
            uint32_t off = (uint32_t)(m * 144 + q * 8);
            *(u64*)(smem + SA_H(buf) + off) = pack4bf_hi(v);
            *(u64*)(smem + SA_L(buf) + off) = pack4bf_lo(v);
        }
    };
    auto stageB = [&](int kc, int nc, int buf) {
        const u64* gh = (nc < 2) ? g_w2fh : g_w2bh;
        const u64* gl = (nc < 2) ? g_w2fl : g_w2bl;
        int nb = (nc & 1) * 128;
#pragma unroll
        for (int idx = tid; idx < 128 * 16; idx += 512) {
            int n = idx >> 4, kq = idx & 15;
            size_t gi = (size_t)(nb + n) * 128 + kc * 16 + kq;
            uint32_t off = (uint32_t)(n * 144 + kq * 8);
            *(u64*)(smem + SB_H(buf) + off) = gh[gi];
            *(u64*)(smem + SB_L(buf) + off) = gl[gi];
        }
    };

    stageA(0, 0);
    stageB(0, 0, 0);
    __syncthreads();

    for (int kc = 0; kc < 8; kc++) {
        int ab = kc & 1;
#pragma unroll
        for (int nc = 0; nc < 4; nc++) {
            int it = kc * 4 + nc;
            int bbuf = it & 1;
            if (it < 31) {
                int nkc = (nc == 3) ? kc + 1 : kc;
                int nnc = (nc == 3) ? 0 : nc + 1;
                stageB(nkc, nnc, bbuf ^ 1);
            }
            if (nc == 0 && kc < 7) stageA(kc + 1, ab ^ 1);
            PJ_COMPUTE(acc[nc], SA_H(ab), SA_L(ab), SB_H(bbuf), SB_L(bbuf));
            __syncthreads();
        }
    }

    // ---- epilogue ----
#pragma unroll
    for (int nc = 0; nc < 4; nc++) {
        float* outp = (nc < 2) ? g_xp2f : g_xp2b;
        const float* bias = (nc < 2) ? g_b2f : g_b2b;
        int nb = (nc & 1) * 128;
#pragma unroll
        for (int mt = 0; mt < 2; mt++)
#pragma unroll
            for (int nt = 0; nt < 2; nt++) {
                int gcol = nb + N0 + nt * 8 + kp2;
                int row0 = tok0 + M0 + mt * 16 + r4;
                float b0 = bias[gcol], b1v = bias[gcol + 1];
                *(float2*)(outp + (size_t)row0 * H + gcol) =
                    make_float2(acc[nc][mt][nt][0] + b0, acc[nc][mt][nt][1] + b1v);
                *(float2*)(outp + (size_t)(row0 + 8) * H + gcol) =
                    make_float2(acc[nc][mt][nt][2] + b0, acc[nc][mt][nt][3] + b1v);
            }
    }
}

// ---------------- layer-1 input projection: HMMA + embedding gather -----------
__global__ __launch_bounds__(512, 1) void proj1_mma_kernel(
    const int* __restrict__ x, const float* __restrict__ emb)
{
    extern __shared__ char smem[];
    int tid = threadIdx.x;
    int wid = tid >> 5, lane = tid & 31;
    int r4 = lane >> 2;
    int kp2 = (lane & 3) * 2;
    int b = blockIdx.x >> 3;
    int tok0 = blockIdx.x * 64;                       // global token base
    int tloc0 = (blockIdx.x & 7) * 64;                // within-batch token base
    int M0 = (wid & 1) * 32;
    int N0 = (wid >> 1) * 16;
    (void)b; (void)tloc0;

    float acc[4][2][2][4];
#pragma unroll
    for (int nc = 0; nc < 4; nc++)
#pragma unroll
        for (int mt = 0; mt < 2; mt++)
#pragma unroll
            for (int nt = 0; nt < 2; nt++)
#pragma unroll
                for (int q = 0; q < 4; q++) acc[nc][mt][nt][q] = 0.f;

    auto stageA = [&](int kc, int buf) {
#pragma unroll
        for (int idx = tid; idx < 64 * 16; idx += 512) {
            int m = idx >> 4, q = idx & 15;
            int token = x[tok0 + m];
            float4 v = *(const float4*)(emb + (size_t)token * 128 + kc * 64 + q * 4);
            uint32_t off = (uint32_t)(m * 144 + q * 8);
            *(u64*)(smem + SA_H(buf) + off) = pack4bf_hi(v);
            *(u64*)(smem + SA_L(buf) + off) = pack4bf_lo(v);
        }
    };
    auto stageB = [&](int kc, int nc, int buf) {
        const u64* gh = (nc < 2) ? g_r1fh : g_r1bh;
        const u64* gl = (nc < 2) ? g_r1fl : g_r1bl;
        int nb = (nc & 1) * 128;
#pragma unroll
        for (int idx = tid; idx < 128 * 16; idx += 512) {
            int n = idx >> 4, kq = idx & 15;
            size_t gi = (size_t)(nb + n) * 32 + kc * 16 + kq;
            uint32_t off = (uint32_t)(n * 144 + kq * 8);
            *(u64*)(smem + SB_H(buf) + off) = gh[gi];
            *(u64*)(smem + SB_L(buf) + off) = gl[gi];
        }
    };

    stageA(0, 0);
    stageB(0, 0, 0);
    __syncthreads();

    for (int kc = 0; kc < 2; kc++) {
        int ab = kc & 1;
#pragma unroll
        for (int nc = 0; nc < 4; nc++) {
            int it = kc * 4 + nc;
            int bbuf = it & 1;
            if (it < 7) {
                int nkc = (nc == 3) ? kc + 1 : kc;
                int nnc = (nc == 3) ? 0 : nc + 1;
                stageB(nkc, nnc, bbuf ^ 1);
            }
            if (nc == 0 && kc < 1) stageA(kc + 1, ab ^ 1);
            PJ_COMPUTE(acc[nc], SA_H(ab), SA_L(ab), SB_H(bbuf), SB_L(bbuf));
            __syncthreads();
        }
    }

#pragma unroll
    for (int nc = 0; nc < 4; nc++) {
        float* outp = (nc < 2) ? g_xp1f : g_xp1b;
        const float* bias = (nc < 2) ? g_b1f : g_b1b;
        int nb = (nc & 1) * 128;
#pragma unroll
        for (int mt = 0; mt < 2; mt++)
#pragma unroll
            for (int nt = 0; nt < 2; nt++) {
                int gcol = nb + N0 + nt * 8 + kp2;
                int row0 = tok0 + M0 + mt * 16 + r4;
                float b0 = bias[gcol], b1v = bias[gcol + 1];
                *(float2*)(outp + (size_t)row0 * H + gcol) =
                    make_float2(acc[nc][mt][nt][0] + b0, acc[nc][mt][nt][1] + b1v);
                *(float2*)(outp + (size_t)(row0 + 8) * H + gcol) =
                    make_float2(acc[nc][mt][nt][2] + b0, acc[nc][mt][nt][3] + b1v);
            }
    }
}

// ---------------- recurrence (unchanged, proven) -------------------------------
constexpr int PREG = 40;
constexpr int PSM = 24;
constexpr int WSLOT = PSM / 2;
constexpr int RNN_SMEM_BYTES = 2 * WSLOT * H * 16 + 2 * H * 4 + H * 4;

__global__ __launch_bounds__(512, 1) void rnn_kernel(
    const float* __restrict__ whh_f, const float* __restrict__ whh_b, int layer)
{
    extern __shared__ char smraw[];
    ulonglong2* wsq = (ulonglong2*)smraw;
    float* hb = (float*)(smraw + 2 * WSLOT * H * 16);
    float* partial = hb + 2 * H;

    int b = blockIdx.x >> 1;
    int dir = blockIdx.x & 1;
    const float* whh = dir ? whh_b : whh_f;
    const float* xp = layer ? (dir ? g_xp2b : g_xp2f) : (dir ? g_xp1b : g_xp1f);
    float* out = layer ? g_o2 : g_o1;

    int j = threadIdx.x & 255;
    int half = threadIdx.x >> 8;

    const u64* wrow = (const u64*)(whh + (size_t)j * H) + half * 64;
    u64 wr[PREG];
#pragma unroll
    for (int r = 0; r < PREG; r++) wr[r] = wrow[r];
#pragma unroll
    for (int i = 0; i < WSLOT; i++) {
        ulonglong2 v;
        v.x = wrow[PREG + 2 * i];
        v.y = wrow[PREG + 2 * i + 1];
        wsq[(half * WSLOT + i) * H + j] = v;
    }
    if (half == 0) { hb[j] = 0.f; hb[H + j] = 0.f; }
    __syncthreads();

    const float* xpBase = xp + (size_t)b * TT * H + j;
    float* outBase = out + (size_t)b * TT * (2 * H) + dir * H + j;
    const ulonglong2* wsBase = wsq + (half * WSLOT) * H + j;

    float xpv = (half == 0) ? xpBase[(size_t)(dir ? (TT - 1) : 0) * H] : 0.f;

    int p = 0;
    for (int s = 0; s < TT; s++) {
        int t = dir ? (TT - 1 - s) : s;
        int sn = (s < TT - 1) ? (s + 1) : s;
        int tn = dir ? (TT - 1 - sn) : sn;
        float xpv_next = (half == 0) ? xpBase[(size_t)tn * H] : 0.f;

        const ulonglong2* h2 = (const ulonglong2*)(hb + p * H) + half * 32;
        u64 a0 = 0ull, a1 = 0ull, a2 = 0ull, a3 = 0ull;
#pragma unroll
        for (int q = 0; q < PREG / 2; q++) {
            ulonglong2 hq = h2[q];
            if (q & 1) {
                a2 = ffma2(hq.x, wr[2 * q], a2);
                a3 = ffma2(hq.y, wr[2 * q + 1], a3);
            } else {
                a0 = ffma2(hq.x, wr[2 * q], a0);
                a1 = ffma2(hq.y, wr[2 * q + 1], a1);
            }
        }
#pragma unroll
        for (int i = 0; i < WSLOT; i++) {
            ulonglong2 hq = h2[PREG / 2 + i];
            ulonglong2 wq = wsBase[i * H];
            if (i & 1) {
                a2 = ffma2(hq.x, wq.x, a2);
                a3 = ffma2(hq.y, wq.y, a3);
            } else {
                a0 = ffma2(hq.x, wq.x, a0);
                a1 = ffma2(hq.y, wq.y, a1);
            }
        }
        float2 f = unpk(fadd2(fadd2(a0, a1), fadd2(a2, a3)));
        float part = f.x + f.y;
        if (half == 1) partial[j] = part;
        __syncthreads();
        if (half == 0) {
            float hn = fast_tanh(part + partial[j] + xpv);
            hb[(p ^ 1) * H + j] = hn;
            outBase[(size_t)t * (2 * H)] = hn;
        }
        __syncthreads();
        xpv = xpv_next;
        p ^= 1;
    }
}

// ---------------- tail (unchanged) --------------------------------------------
__global__ __launch_bounds__(256) void tail_kernel(
    const float* __restrict__ ln_g, const float* __restrict__ ln_b,
    const float* __restrict__ b1, const float* __restrict__ b2,
    float* __restrict__ outp)
{
    __shared__ __align__(16) float h_s[1024];
    __shared__ __align__(16) float hn_s[1024];
    __shared__ float red[256];
    __shared__ __align__(16) float r_s[512];
    int b = blockIdx.x, j = threadIdx.x;

    const float* base = g_o2 + (size_t)b * TT * (2 * H);
    float s0 = 0.f, s1 = 0.f;
    for (int t = 0; t < TT; t++) {
        s0 += base[(size_t)t * (2 * H) + j];
        s1 += base[(size_t)t * (2 * H) + H + j];
    }
    h_s[j]       = base[(size_t)(TT - 1) * (2 * H) + j];
    h_s[H + j]   = base[(size_t)(TT - 1) * (2 * H) + H + j];
    h_s[512 + j] = s0 * (1.f / 512.f);
    h_s[768 + j] = s1 * (1.f / 512.f);
    __syncthreads();

    red[j] = h_s[j] + h_s[j + 256] + h_s[j + 512] + h_s[j + 768];
    __syncthreads();
    for (int off = 128; off > 0; off >>= 1) {
        if (j < off) red[j] += red[j + off];
        __syncthreads();
    }
    float mu = red[0] * (1.f / 1024.f);
    __syncthreads();
    float d0 = h_s[j] - mu, d1 = h_s[j + 256] - mu,
          d2 = h_s[j + 512] - mu, d3 = h_s[j + 768] - mu;
    red[j] = d0 * d0 + d1 * d1 + d2 * d2 + d3 * d3;
    __syncthreads();
    for (int off = 128; off > 0; off >>= 1) {
        if (j < off) red[j] += red[j + off];
        __syncthreads();
    }
    float var = red[0] * (1.f / 1024.f);
    float sc = rsqrtf(var + 1e-5f);
    hn_s[j]       = d0 * sc * ln_g[j]       + ln_b[j];
    hn_s[j + 256] = d1 * sc * ln_g[j + 256] + ln_b[j + 256];
    hn_s[j + 512] = d2 * sc * ln_g[j + 512] + ln_b[j + 512];
    hn_s[j + 768] = d3 * sc * ln_g[j + 768] + ln_b[j + 768];
    __syncthreads();

    {
        const u64* hnu = (const u64*)hn_s;
        const u64* w1u = (const u64*)g_w1p;
        u64 acc0 = 0ull, acc1 = 0ull;
#pragma unroll 4
        for (int kp = 0; kp < 512; kp++) {
            u64 hv = hnu[kp];
            acc0 = ffma2(hv, w1u[kp * 512 + j], acc0);
            acc1 = ffma2(hv, w1u[kp * 512 + j + 256], acc1);
        }
        float2 f0 = unpk(acc0), f1 = unpk(acc1);
        r_s[j]       = fmaxf(f0.x + f0.y + b1[j], 0.f);
        r_s[j + 256] = fmaxf(f1.x + f1.y + b1[j + 256], 0.f);
    }
    __syncthreads();

    {
        const u64* rsu = (const u64*)r_s;
        const u64* w2u = (const u64*)g_w2p;
        u64 acc = 0ull;
#pragma unroll 4
        for (int kp = 0; kp < 256; kp++)
            acc = ffma2(rsu[kp], w2u[kp * 256 + j], acc);
        float2 f = unpk(acc);
        outp[b * 256 + j] = f.x + f.y + b2[j];
    }
}

// ---------------- launch ------------------------------------------------------
extern "C" void kernel_launch(void* const* d_in, const int* in_sizes, int n_in,
                              void* d_out, int out_size)
{
    const int*   x      = (const int*)  d_in[0];
    const float* emb    = (const float*)d_in[1];
    const float* r1_wif = (const float*)d_in[2];
    const float* r1_whf = (const float*)d_in[3];
    const float* r1_bif = (const float*)d_in[4];
    const float* r1_bhf = (const float*)d_in[5];
    const float* r1_wib = (const float*)d_in[6];
    const float* r1_whb = (const float*)d_in[7];
    const float* r1_bib = (const float*)d_in[8];
    const float* r1_bhb = (const float*)d_in[9];
    const float* r2_wif = (const float*)d_in[10];
    const float* r2_whf = (const float*)d_in[11];
    const float* r2_bif = (const float*)d_in[12];
    const float* r2_bhf = (const float*)d_in[13];
    const float* r2_wib = (const float*)d_in[14];
    const float* r2_whb = (const float*)d_in[15];
    const float* r2_bib = (const float*)d_in[16];
    const float* r2_bhb = (const float*)d_in[17];
    const float* ln_g   = (const float*)d_in[18];
    const float* ln_b   = (const float*)d_in[19];
    const float* w1     = (const float*)d_in[20];
    const float* b1     = (const float*)d_in[21];
    const float* w2     = (const float*)d_in[22];
    const float* b2     = (const float*)d_in[23];
    float* outp = (float*)d_out;

    cudaFuncSetAttribute(rnn_kernel,
                         cudaFuncAttributeMaxDynamicSharedMemorySize,
                         RNN_SMEM_BYTES);
    cudaFuncSetAttribute(proj2_mma_kernel,
                         cudaFuncAttributeMaxDynamicSharedMemorySize,
                         PJ_SMEM);
    cudaFuncSetAttribute(proj1_mma_kernel,
                         cudaFuncAttributeMaxDynamicSharedMemorySize,
                         PJ_SMEM);

    prep_kernel<<<1024, 256>>>(r1_wif, r1_wib, r1_bif, r1_bhf, r1_bib, r1_bhb,
                               r2_wif, r2_wib, r2_bif, r2_bhf, r2_bib, r2_bhb,
                               w1, w2);

    proj1_mma_kernel<<<(B * TT) / 64, 512, PJ_SMEM>>>(x, emb);
    rnn_kernel<<<2 * B, 512, RNN_SMEM_BYTES>>>(r1_whf, r1_whb, 0);
    proj2_mma_kernel<<<(B * TT) / 64, 512, PJ_SMEM>>>();
    rnn_kernel<<<2 * B, 512, RNN_SMEM_BYTES>>>(r2_whf, r2_whb, 1);
    tail_kernel<<<B, 256>>>(ln_g, ln_b, b1, b2, outp);
}

// round 16
// speedup vs baseline: 1.1485x; 1.0035x over previous
#include <cuda_runtime.h>
#include <cuda_bf16.h>
#include <math.h>
#include <stdint.h>

#define B 64
#define TT 512
#define E 128
#define H 256

typedef unsigned long long u64;

// ---------------- packed f32x2 helpers ----------------------------------------
__device__ __forceinline__ u64 ffma2(u64 a, u64 b, u64 c) {
    u64 d;
    asm("fma.rn.f32x2 %0, %1, %2, %3;" : "=l"(d) : "l"(a), "l"(b), "l"(c));
    return d;
}
__device__ __forceinline__ u64 fadd2(u64 a, u64 b) {
    u64 d;
    asm("add.rn.f32x2 %0, %1, %2;" : "=l"(d) : "l"(a), "l"(b));
    return d;
}
__device__ __forceinline__ float2 unpk(u64 v) {
    float2 r;
    asm("mov.b64 {%0, %1}, %2;" : "=f"(r.x), "=f"(r.y) : "l"(v));
    return r;
}
__device__ __forceinline__ float fast_tanh(float x) {
    float e, r;
    asm("ex2.approx.f32 %0, %1;" : "=f"(e) : "f"(x * 2.885390081777927f));
    asm("rcp.approx.f32 %0, %1;" : "=f"(r) : "f"(e + 1.0f));
    return fmaf(-2.0f, r, 1.0f);
}

// bf16 hi/lo packing (4 values per u64)
__device__ __forceinline__ u64 pack4bf_hi(float4 v) {
    unsigned short s0 = __bfloat16_as_ushort(__float2bfloat16(v.x));
    unsigned short s1 = __bfloat16_as_ushort(__float2bfloat16(v.y));
    unsigned short s2 = __bfloat16_as_ushort(__float2bfloat16(v.z));
    unsigned short s3 = __bfloat16_as_ushort(__float2bfloat16(v.w));
    return (u64)s0 | ((u64)s1 << 16) | ((u64)s2 << 32) | ((u64)s3 << 48);
}
__device__ __forceinline__ u64 pack4bf_lo(float4 v) {
    float r0 = v.x - __bfloat162float(__float2bfloat16(v.x));
    float r1 = v.y - __bfloat162float(__float2bfloat16(v.y));
    float r2 = v.z - __bfloat162float(__float2bfloat16(v.z));
    float r3 = v.w - __bfloat162float(__float2bfloat16(v.w));
    unsigned short s0 = __bfloat16_as_ushort(__float2bfloat16(r0));
    unsigned short s1 = __bfloat16_as_ushort(__float2bfloat16(r1));
    unsigned short s2 = __bfloat16_as_ushort(__float2bfloat16(r2));
    unsigned short s3 = __bfloat16_as_ushort(__float2bfloat16(r3));
    return (u64)s0 | ((u64)s1 << 16) | ((u64)s2 << 32) | ((u64)s3 << 48);
}

// warp-level bf16 MMA (sm_80+ path, valid on plain sm_103) — layout proven R14
#define MMA_BF16(c, a0, a1, a2, a3, b0, b1)                                    \
    asm volatile(                                                              \
        "mma.sync.aligned.m16n8k16.row.col.f32.bf16.bf16.f32 "                 \
        "{%0,%1,%2,%3}, {%4,%5,%6,%7}, {%8,%9}, {%0,%1,%2,%3};\n"              \
        : "+f"((c)[0]), "+f"((c)[1]), "+f"((c)[2]), "+f"((c)[3])               \
        : "r"(a0), "r"(a1), "r"(a2), "r"(a3), "r"(b0), "r"(b1))

// cp.async (sm_80+ path)
#define CP_ASYNC16(saddr, gptr)                                                \
    asm volatile("cp.async.ca.shared.global [%0], [%1], 16;"                   \
                 :: "r"(saddr), "l"(gptr) : "memory")
#define CP_COMMIT() asm volatile("cp.async.commit_group;" ::: "memory")
#define CP_WAIT1()  asm volatile("cp.async.wait_group 1;" ::: "memory")
#define CP_WAIT0()  asm volatile("cp.async.wait_group 0;" ::: "memory")

// ---------------- scratch (device globals) ------------------------------------
__device__ float g_xp1f[(size_t)B * TT * H];
__device__ float g_xp1b[(size_t)B * TT * H];
__device__ float g_o1[(size_t)B * TT * 2 * H];
__device__ float g_xp2f[(size_t)B * TT * H];
__device__ float g_xp2b[(size_t)B * TT * H];
__device__ float g_o2[(size_t)B * TT * 2 * H];   // layer-2 dummy target (unused)

__device__ float g_msum[2 * B * H];              // per (b,dir): sum_t h
__device__ float g_last[2 * B * H];              // per (b,dir): h at t=TT-1

__device__ float2 g_w1p[512 * 512];
__device__ float2 g_w2p[256 * 256];
__device__ float g_b1f[H], g_b1b[H], g_b2f[H], g_b2b[H];

// bf16 hi/lo split weights. layer2 in-proj: [n=256][k512/4=128] u64
__device__ u64 g_w2fh[256 * 128];
__device__ u64 g_w2fl[256 * 128];
__device__ u64 g_w2bh[256 * 128];
__device__ u64 g_w2bl[256 * 128];
// layer1 in-proj: [n=256][k128/4=32] u64
__device__ u64 g_r1fh[256 * 32];
__device__ u64 g_r1fl[256 * 32];
__device__ u64 g_r1bh[256 * 32];
__device__ u64 g_r1bl[256 * 32];

// ---------------- prep --------------------------------------------------------
__global__ void prep_kernel(
    const float* __restrict__ r1_wif, const float* __restrict__ r1_wib,
    const float* __restrict__ r1_bif, const float* __restrict__ r1_bhf,
    const float* __restrict__ r1_bib, const float* __restrict__ r1_bhb,
    const float* __restrict__ r2_wif, const float* __restrict__ r2_wib,
    const float* __restrict__ r2_bif, const float* __restrict__ r2_bhf,
    const float* __restrict__ r2_bib, const float* __restrict__ r2_bhb,
    const float* __restrict__ w1, const float* __restrict__ w2)
{
    int i = blockIdx.x * 256 + threadIdx.x;
    if (i < 256 * 32) {
        float4 vf = *(const float4*)(r1_wif + (size_t)i * 4);
        float4 vb = *(const float4*)(r1_wib + (size_t)i * 4);
        g_r1fh[i] = pack4bf_hi(vf);
        g_r1fl[i] = pack4bf_lo(vf);
        g_r1bh[i] = pack4bf_hi(vb);
        g_r1bl[i] = pack4bf_lo(vb);
    }
    if (i < 256 * H) {
        int kp = i >> 8, j = i & 255;
        g_w2p[i] = make_float2(w2[j * 512 + 2 * kp], w2[j * 512 + 2 * kp + 1]);
    }
    if (i < 256 * 128) {
        float4 vf = *(const float4*)(r2_wif + (size_t)i * 4);
        float4 vb = *(const float4*)(r2_wib + (size_t)i * 4);
        g_w2fh[i] = pack4bf_hi(vf);
        g_w2fl[i] = pack4bf_lo(vf);
        g_w2bh[i] = pack4bf_hi(vb);
        g_w2bl[i] = pack4bf_lo(vb);
    }
    if (i < 512 * 512) {
        int kp = i >> 9, o = i & 511;
        g_w1p[i] = make_float2(w1[o * 1024 + 2 * kp], w1[o * 1024 + 2 * kp + 1]);
    }
    if (i < H) {
        g_b1f[i] = r1_bif[i] + r1_bhf[i];
        g_b1b[i] = r1_bib[i] + r1_bhb[i];
        g_b2f[i] = r2_bif[i] + r2_bhf[i];
        g_b2b[i] = r2_bib[i] + r2_bhb[i];
    }
}

// ---------------- shared MMA-projection geometry -------------------------------
// A chunk: 64 rows x 64 k bf16, row stride 72 elems (bank-conflict-free).
// B chunk: 128 rows x 64 k bf16, stride 72.
static constexpr int SA_SZ = 64 * 72 * 2;            // 9216
static constexpr int SB_SZ = 128 * 72 * 2;           // 18432
#define SA_H(buf) ((buf) * 2 * SA_SZ)
#define SA_L(buf) ((buf) * 2 * SA_SZ + SA_SZ)
// proj1 (2 B bufs, LDG+STS path)
static constexpr int SB_BASE = 4 * SA_SZ;            // 36864
static constexpr int PJ1_SMEM = SB_BASE + 4 * SB_SZ; // 110592
#define SB_H(buf) (SB_BASE + (buf) * 2 * SB_SZ)
#define SB_L(buf) (SB_BASE + (buf) * 2 * SB_SZ + SB_SZ)
// proj2 (3 B bufs, cp.async path)
static constexpr int PJ2_SMEM = SB_BASE + 6 * SB_SZ; // 147456
#define SB3_H(buf) (SB_BASE + (buf) * 2 * SB_SZ)
#define SB3_L(buf) (SB_BASE + (buf) * 2 * SB_SZ + SB_SZ)

// compute one (m64 x n128 x k64) stage into acc[2][2][4]
#define PJ_COMPUTE(accn, sah, sal, sbh, sbl)                                   \
    do {                                                                       \
        _Pragma("unroll")                                                      \
        for (int ks = 0; ks < 4; ks++) {                                       \
            uint32_t ah[2][4], al[2][4];                                       \
            _Pragma("unroll")                                                  \
            for (int mt = 0; mt < 2; mt++) {                                   \
                uint32_t ba = (uint32_t)(((M0 + mt * 16 + r4) * 72 + ks * 16 + kp2) * 2); \
                ah[mt][0] = *(const uint32_t*)(smem + (sah) + ba);             \
                ah[mt][1] = *(const uint32_t*)(smem + (sah) + ba + 1152);      \
                ah[mt][2] = *(const uint32_t*)(smem + (sah) + ba + 16);        \
                ah[mt][3] = *(const uint32_t*)(smem + (sah) + ba + 1168);      \
                al[mt][0] = *(const uint32_t*)(smem + (sal) + ba);             \
                al[mt][1] = *(const uint32_t*)(smem + (sal) + ba + 1152);      \
                al[mt][2] = *(const uint32_t*)(smem + (sal) + ba + 16);        \
                al[mt][3] = *(const uint32_t*)(smem + (sal) + ba + 1168);      \
            }                                                                  \
            _Pragma("unroll")                                                  \
            for (int nt = 0; nt < 2; nt++) {                                   \
                uint32_t bb = (uint32_t)(((N0 + nt * 8 + r4) * 72 + ks * 16 + kp2) * 2); \
                uint32_t bh0 = *(const uint32_t*)(smem + (sbh) + bb);          \
                uint32_t bh1 = *(const uint32_t*)(smem + (sbh) + bb + 16);     \
                uint32_t bl0 = *(const uint32_t*)(smem + (sbl) + bb);          \
                uint32_t bl1 = *(const uint32_t*)(smem + (sbl) + bb + 16);     \
                _Pragma("unroll")                                              \
                for (int mt = 0; mt < 2; mt++) {                               \
                    MMA_BF16((accn)[mt][nt], ah[mt][0], ah[mt][1], ah[mt][2], ah[mt][3], bh0, bh1); \
                    MMA_BF16((accn)[mt][nt], ah[mt][0], ah[mt][1], ah[mt][2], ah[mt][3], bl0, bl1); \
                    MMA_BF16((accn)[mt][nt], al[mt][0], al[mt][1], al[mt][2], al[mt][3], bh0, bh1); \
                }                                                              \
            }                                                                  \
        }                                                                      \
    } while (0)

__device__ __forceinline__ uint32_t smem_u32(const void* p) {
    uint32_t a;
    asm("{ .reg .u64 t; cvta.to.shared.u64 t, %1; cvt.u32.u64 %0, t; }"
        : "=r"(a) : "l"(p));
    return a;
}

// ---------------- layer-2 input projection: HMMA + cp.async pipeline ----------
__global__ __launch_bounds__(512, 1) void proj2_mma_kernel()
{
    extern __shared__ char smem[];
    uint32_t sbase = smem_u32(smem);
    int tid = threadIdx.x;
    int wid = tid >> 5, lane = tid & 31;
    int r4 = lane >> 2;
    int kp2 = (lane & 3) * 2;
    int tok0 = blockIdx.x * 64;
    int M0 = (wid & 1) * 32;
    int N0 = (wid >> 1) * 16;

    float acc[4][2][2][4];
#pragma unroll
    for (int nc = 0; nc < 4; nc++)
#pragma unroll
        for (int mt = 0; mt < 2; mt++)
#pragma unroll
            for (int nt = 0; nt < 2; nt++)
#pragma unroll
                for (int q = 0; q < 4; q++) acc[nc][mt][nt][q] = 0.f;

    // ---- B staging via cp.async: 128 rows x 8 16B-chunks (hi and lo) ----
    auto stageB = [&](int it, int buf) {
        int kc = it >> 2, nc = it & 3;
        const u64* gh = (nc < 2) ? g_w2fh : g_w2bh;
        const u64* gl = (nc < 2) ? g_w2fl : g_w2bl;
        int nb = (nc & 1) * 128;
#pragma unroll
        for (int r = 0; r < 2; r++) {
            int idx = tid + r * 512;          // 0..1023
            int n = idx >> 3, kq2 = idx & 7;  // 16B chunk
            size_t gi = (size_t)(nb + n) * 128 + kc * 16 + kq2 * 2;
            uint32_t off = (uint32_t)(n * 144 + kq2 * 16);
            CP_ASYNC16(sbase + SB3_H(buf) + off, gh + gi);
            CP_ASYNC16(sbase + SB3_L(buf) + off, gl + gi);
        }
    };
    // ---- A staging: LDG to regs early, pack+STS late ----
    auto ldA = [&](int kc, float4* av) {
#pragma unroll
        for (int r = 0; r < 2; r++) {
            int idx = tid + r * 512;
            int m = idx >> 4, q = idx & 15;
            av[r] = *(const float4*)(g_o1 + (size_t)(tok0 + m) * 512 + kc * 64 + q * 4);
        }
    };
    auto stsA = [&](const float4* av, int buf) {
#pragma unroll
        for (int r = 0; r < 2; r++) {
            int idx = tid + r * 512;
            int m = idx >> 4, q = idx & 15;
            uint32_t off = (uint32_t)(m * 144 + q * 8);
            *(u64*)(smem + SA_H(buf) + off) = pack4bf_hi(av[r]);
            *(u64*)(smem + SA_L(buf) + off) = pack4bf_lo(av[r]);
        }
    };

    float4 av[2];
    // prologue: A(0) staged; B(0), B(1) in flight; wait B(0)
    ldA(0, av);
    stageB(0, 0); CP_COMMIT();
    stageB(1, 1); CP_COMMIT();
    stsA(av, 0);
    CP_WAIT1();
    __syncthreads();

    for (int it = 0; it < 32; it++) {
        int kc = it >> 2, nc = it & 3;
        if (it + 2 < 32) { stageB(it + 2, (it + 2) % 3); CP_COMMIT(); }
        if (nc == 0 && kc < 7) ldA(kc + 1, av);
        PJ_COMPUTE(acc[nc], SA_H(kc & 1), SA_L(kc & 1), SB3_H(it % 3), SB3_L(it % 3));
        if (nc == 3 && kc < 7) stsA(av, (kc + 1) & 1);
        if (it < 30) { CP_WAIT1(); } else { CP_WAIT0(); }
        __syncthreads();
    }

    // ---- epilogue ----
#pragma unroll
    for (int nc = 0; nc < 4; nc++) {
        float* outp = (nc < 2) ? g_xp2f : g_xp2b;
        const float* bias = (nc < 2) ? g_b2f : g_b2b;
        int nb = (nc & 1) * 128;
#pragma unroll
        for (int mt = 0; mt < 2; mt++)
#pragma unroll
            for (int nt = 0; nt < 2; nt++) {
                int gcol = nb + N0 + nt * 8 + kp2;
                int row0 = tok0 + M0 + mt * 16 + r4;
                float b0 = bias[gcol], b1v = bias[gcol + 1];
                *(float2*)(outp + (size_t)row0 * H + gcol) =
                    make_float2(acc[nc][mt][nt][0] + b0, acc[nc][mt][nt][1] + b1v);
                *(float2*)(outp + (size_t)(row0 + 8) * H + gcol) =
                    make_float2(acc[nc][mt][nt][2] + b0, acc[nc][mt][nt][3] + b1v);
            }
    }
}

// ---------------- layer-1 input projection: HMMA (R15-proven) -----------------
__global__ __launch_bounds__(512, 1) void proj1_mma_kernel(
    const int* __restrict__ x, const float* __restrict__ emb)
{
    extern __shared__ char smem[];
    int tid = threadIdx.x;
    int wid = tid >> 5, lane = tid & 31;
    int r4 = lane >> 2;
    int kp2 = (lane & 3) * 2;
    int tok0 = blockIdx.x * 64;
    int M0 = (wid & 1) * 32;
    int N0 = (wid >> 1) * 16;

    float acc[4][2][2][4];
#pragma unroll
    for (int nc = 0; nc < 4; nc++)
#pragma unroll
        for (int mt = 0; mt < 2; mt++)
#pragma unroll
            for (int nt = 0; nt < 2; nt++)
#pragma unroll
                for (int q = 0; q < 4; q++) acc[nc][mt][nt][q] = 0.f;

    auto stageA = [&](int kc, int buf) {
#pragma unroll
        for (int idx = tid; idx < 64 * 16; idx += 512) {
            int m = idx >> 4, q = idx & 15;
            int token = x[tok0 + m];
            float4 v = *(const float4*)(emb + (size_t)token * 128 + kc * 64 + q * 4);
            uint32_t off = (uint32_t)(m * 144 + q * 8);
            *(u64*)(smem + SA_H(buf) + off) = pack4bf_hi(v);
            *(u64*)(smem + SA_L(buf) + off) = pack4bf_lo(v);
        }
    };
    auto stageB = [&](int kc, int nc, int buf) {
        const u64* gh = (nc < 2) ? g_r1fh : g_r1bh;
        const u64* gl = (nc < 2) ? g_r1fl : g_r1bl;
        int nb = (nc & 1) * 128;
#pragma unroll
        for (int idx = tid; idx < 128 * 16; idx += 512) {
            int n = idx >> 4, kq = idx & 15;
            size_t gi = (size_t)(nb + n) * 32 + kc * 16 + kq;
            uint32_t off = (uint32_t)(n * 144 + kq * 8);
            *(u64*)(smem + SB_H(buf) + off) = gh[gi];
            *(u64*)(smem + SB_L(buf) + off) = gl[gi];
        }
    };

    stageA(0, 0);
    stageB(0, 0, 0);
    __syncthreads();

    for (int kc = 0; kc < 2; kc++) {
        int ab = kc & 1;
#pragma unroll
        for (int nc = 0; nc < 4; nc++) {
            int it = kc * 4 + nc;
            int bbuf = it & 1;
            if (it < 7) {
                int nkc = (nc == 3) ? kc + 1 : kc;
                int nnc = (nc == 3) ? 0 : nc + 1;
                stageB(nkc, nnc, bbuf ^ 1);
            }
            if (nc == 0 && kc < 1) stageA(kc + 1, ab ^ 1);
            PJ_COMPUTE(acc[nc], SA_H(ab), SA_L(ab), SB_H(bbuf), SB_L(bbuf));
            __syncthreads();
        }
    }

#pragma unroll
    for (int nc = 0; nc < 4; nc++) {
        float* outp = (nc < 2) ? g_xp1f : g_xp1b;
        const float* bias = (nc < 2) ? g_b1f : g_b1b;
        int nb = (nc & 1) * 128;
#pragma unroll
        for (int mt = 0; mt < 2; mt++)
#pragma unroll
            for (int nt = 0; nt < 2; nt++) {
                int gcol = nb + N0 + nt * 8 + kp2;
                int row0 = tok0 + M0 + mt * 16 + r4;
                float b0 = bias[gcol], b1v = bias[gcol + 1];
                *(float2*)(outp + (size_t)row0 * H + gcol) =
                    make_float2(acc[nc][mt][nt][0] + b0, acc[nc][mt][nt][1] + b1v);
                *(float2*)(outp + (size_t)(row0 + 8) * H + gcol) =
                    make_float2(acc[nc][mt][nt][2] + b0, acc[nc][mt][nt][3] + b1v);
            }
    }
}

// ---------------- recurrence (R11 structure + layer-2 mean/last fusion) -------
constexpr int PREG = 40;
constexpr int PSM = 24;
constexpr int WSLOT = PSM / 2;
constexpr int RNN_SMEM_BYTES = 2 * WSLOT * H * 16 + 2 * H * 4 + H * 4;

__global__ __launch_bounds__(512, 1) void rnn_kernel(
    const float* __restrict__ whh_f, const float* __restrict__ whh_b, int layer)
{
    extern __shared__ char smraw[];
    ulonglong2* wsq = (ulonglong2*)smraw;
    float* hb = (float*)(smraw + 2 * WSLOT * H * 16);
    float* partial = hb + 2 * H;

    int b = blockIdx.x >> 1;
    int dir = blockIdx.x & 1;
    const float* whh = dir ? whh_b : whh_f;
    const float* xp = layer ? (dir ? g_xp2b : g_xp2f) : (dir ? g_xp1b : g_xp1f);
    float* out = layer ? g_o2 : g_o1;

    int j = threadIdx.x & 255;
    int half = threadIdx.x >> 8;

    const u64* wrow = (const u64*)(whh + (size_t)j * H) + half * 64;
    u64 wr[PREG];
#pragma unroll
    for (int r = 0; r < PREG; r++) wr[r] = wrow[r];
#pragma unroll
    for (int i = 0; i < WSLOT; i++) {
        ulonglong2 v;
        v.x = wrow[PREG + 2 * i];
        v.y = wrow[PREG + 2 * i + 1];
        wsq[(half * WSLOT + i) * H + j] = v;
    }
    if (half == 0) { hb[j] = 0.f; hb[H + j] = 0.f; }
    __syncthreads();

    const float* xpBase = xp + (size_t)b * TT * H + j;
    float* outBase = out + (size_t)b * TT * (2 * H) + dir * H + j;
    const ulonglong2* wsBase = wsq + (half * WSLOT) * H + j;

    float xpv = (half == 0) ? xpBase[(size_t)(dir ? (TT - 1) : 0) * H] : 0.f;
    int lastS = dir ? 0 : (TT - 1);
    float hsum = 0.f, hlast = 0.f;

    int p = 0;
    for (int s = 0; s < TT; s++) {
        int t = dir ? (TT - 1 - s) : s;
        int sn = (s < TT - 1) ? (s + 1) : s;
        int tn = dir ? (TT - 1 - sn) : sn;
        float xpv_next = (half == 0) ? xpBase[(size_t)tn * H] : 0.f;

        const ulonglong2* h2 = (const ulonglong2*)(hb + p * H) + half * 32;
        u64 a0 = 0ull, a1 = 0ull, a2 = 0ull, a3 = 0ull;
#pragma unroll
        for (int q = 0; q < PREG / 2; q++) {
            ulonglong2 hq = h2[q];
            if (q & 1) {
                a2 = ffma2(hq.x, wr[2 * q], a2);
                a3 = ffma2(hq.y, wr[2 * q + 1], a3);
            } else {
                a0 = ffma2(hq.x, wr[2 * q], a0);
                a1 = ffma2(hq.y, wr[2 * q + 1], a1);
            }
        }
#pragma unroll
        for (int i = 0; i < WSLOT; i++) {
            ulonglong2 hq = h2[PREG / 2 + i];
            ulonglong2 wq = wsBase[i * H];
            if (i & 1) {
                a2 = ffma2(hq.x, wq.x, a2);
                a3 = ffma2(hq.y, wq.y, a3);
            } else {
                a0 = ffma2(hq.x, wq.x, a0);
                a1 = ffma2(hq.y, wq.y, a1);
            }
        }
        float2 f = unpk(fadd2(fadd2(a0, a1), fadd2(a2, a3)));
        float part = f.x + f.y;
        if (half == 1) partial[j] = part;
        __syncthreads();
        if (half == 0) {
            float hn = fast_tanh(part + partial[j] + xpv);
            hb[(p ^ 1) * H + j] = hn;
            if (layer == 0) {
                outBase[(size_t)t * (2 * H)] = hn;
            } else {
                hsum += hn;
                hlast = (s == lastS) ? hn : hlast;
            }
        }
        __syncthreads();
        xpv = xpv_next;
        p ^= 1;
    }

    if (layer != 0 && half == 0) {
        g_msum[(b * 2 + dir) * H + j] = hsum;
        g_last[(b * 2 + dir) * H + j] = hlast;
    }
}

// ---------------- tail: small-array read + LN + FC1(relu) + FC2 ---------------
__global__ __launch_bounds__(256) void tail_kernel(
    const float* __restrict__ ln_g, const float* __restrict__ ln_b,
    const float* __restrict__ b1, const float* __restrict__ b2,
    float* __restrict__ outp)
{
    __shared__ __align__(16) float h_s[1024];
    __shared__ __align__(16) float hn_s[1024];
    __shared__ float red[256];
    __shared__ __align__(16) float r_s[512];
    int b = blockIdx.x, j = threadIdx.x;

    h_s[j]       = g_last[(b * 2 + 0) * H + j];
    h_s[H + j]   = g_last[(b * 2 + 1) * H + j];
    h_s[512 + j] = g_msum[(b * 2 + 0) * H + j] * (1.f / 512.f);
    h_s[768 + j] = g_msum[(b * 2 + 1) * H + j] * (1.f / 512.f);
    __syncthreads();

    red[j] = h_s[j] + h_s[j + 256] + h_s[j + 512] + h_s[j + 768];
    __syncthreads();
    for (int off = 128; off > 0; off >>= 1) {
        if (j < off) red[j] += red[j + off];
        __syncthreads();
    }
    float mu = red[0] * (1.f / 1024.f);
    __syncthreads();
    float d0 = h_s[j] - mu, d1 = h_s[j + 256] - mu,
          d2 = h_s[j + 512] - mu, d3 = h_s[j + 768] - mu;
    red[j] = d0 * d0 + d1 * d1 + d2 * d2 + d3 * d3;
    __syncthreads();
    for (int off = 128; off > 0; off >>= 1) {
        if (j < off) red[j] += red[j + off];
        __syncthreads();
    }
    float var = red[0] * (1.f / 1024.f);
    float sc = rsqrtf(var + 1e-5f);
    hn_s[j]       = d0 * sc * ln_g[j]       + ln_b[j];
    hn_s[j + 256] = d1 * sc * ln_g[j + 256] + ln_b[j + 256];
    hn_s[j + 512] = d2 * sc * ln_g[j + 512] + ln_b[j + 512];
    hn_s[j + 768] = d3 * sc * ln_g[j + 768] + ln_b[j + 768];
    __syncthreads();

    {
        const u64* hnu = (const u64*)hn_s;
        const u64* w1u = (const u64*)g_w1p;
        u64 acc0 = 0ull, acc1 = 0ull;
#pragma unroll 4
        for (int kp = 0; kp < 512; kp++) {
            u64 hv = hnu[kp];
            acc0 = ffma2(hv, w1u[kp * 512 + j], acc0);
            acc1 = ffma2(hv, w1u[kp * 512 + j + 256], acc1);
        }
        float2 f0 = unpk(acc0), f1 = unpk(acc1);
        r_s[j]       = fmaxf(f0.x + f0.y + b1[j], 0.f);
        r_s[j + 256] = fmaxf(f1.x + f1.y + b1[j + 256], 0.f);
    }
    __syncthreads();

    {
        const u64* rsu = (const u64*)r_s;
        const u64* w2u = (const u64*)g_w2p;
        u64 acc = 0ull;
#pragma unroll 4
        for (int kp = 0; kp < 256; kp++)
            acc = ffma2(rsu[kp], w2u[kp * 256 + j], acc);
        float2 f = unpk(acc);
        outp[b * 256 + j] = f.x + f.y + b2[j];
    }
}

// ---------------- launch ------------------------------------------------------
extern "C" void kernel_launch(void* const* d_in, const int* in_sizes, int n_in,
                              void* d_out, int out_size)
{
    const int*   x      = (const int*)  d_in[0];
    const float* emb    = (const float*)d_in[1];
    const float* r1_wif = (const float*)d_in[2];
    const float* r1_whf = (const float*)d_in[3];
    const float* r1_bif = (const float*)d_in[4];
    const float* r1_bhf = (const float*)d_in[5];
    const float* r1_wib = (const float*)d_in[6];
    const float* r1_whb = (const float*)d_in[7];
    const float* r1_bib = (const float*)d_in[8];
    const float* r1_bhb = (const float*)d_in[9];
    const float* r2_wif = (const float*)d_in[10];
    const float* r2_whf = (const float*)d_in[11];
    const float* r2_bif = (const float*)d_in[12];
    const float* r2_bhf = (const float*)d_in[13];
    const float* r2_wib = (const float*)d_in[14];
    const float* r2_whb = (const float*)d_in[15];
    const float* r2_bib = (const float*)d_in[16];
    const float* r2_bhb = (const float*)d_in[17];
    const float* ln_g   = (const float*)d_in[18];
    const float* ln_b   = (const float*)d_in[19];
    const float* w1     = (const float*)d_in[20];
    const float* b1     = (const float*)d_in[21];
    const float* w2     = (const float*)d_in[22];
    const float* b2     = (const float*)d_in[23];
    float* outp = (float*)d_out;

    cudaFuncSetAttribute(rnn_kernel,
                         cudaFuncAttributeMaxDynamicSharedMemorySize,
                         RNN_SMEM_BYTES);
    cudaFuncSetAttribute(proj2_mma_kernel,
                         cudaFuncAttributeMaxDynamicSharedMemorySize,
                         PJ2_SMEM);
    cudaFuncSetAttribute(proj1_mma_kernel,
                         cudaFuncAttributeMaxDynamicSharedMemorySize,
                         PJ1_SMEM);

    prep_kernel<<<1024, 256>>>(r1_wif, r1_wib, r1_bif, r1_bhf, r1_bib, r1_bhb,
                               r2_wif, r2_wib, r2_bif, r2_bhf, r2_bib, r2_bhb,
                               w1, w2);

    proj1_mma_kernel<<<(B * TT) / 64, 512, PJ1_SMEM>>>(x, emb);
    rnn_kernel<<<2 * B, 512, RNN_SMEM_BYTES>>>(r1_whf, r1_whb, 0);
    proj2_mma_kernel<<<(B * TT) / 64, 512, PJ2_SMEM>>>();
    rnn_kernel<<<2 * B, 512, RNN_SMEM_BYTES>>>(r2_whf, r2_whb, 1);
    tail_kernel<<<B, 256>>>(ln_g, ln_b, b1, b2, outp);
}